// round 7
// baseline (speedup 1.0000x reference)
#include <cuda_runtime.h>
#include <cuda_bf16.h>
#include <math.h>

// Problem constants
#define SS 128   // sequence length
#define BB 32    // batch
#define CC 16    // chars per word
#define DW 256   // word emb dim
#define DC 64    // char emb dim
#define HC2 64   // char hidden per dir
#define HW2 256  // word hidden per dir
#define NT 17    // tags

// ---------------- scratch (static device memory; no allocations) ----------------
__device__ float g_cWP[2][128][64][4];          // char weights permuted [dir][k][unit][ifgo]
__device__ float g_WIP[2][384][256][4];         // word Wih permuted    [dir][k][unit][ifgo]
__device__ float g_WHP[2][256][256][4];         // word Whh permuted    [dir][k][unit][ifgo]
__device__ float g_x[SS * BB * 384];            // word-LSTM input  [s][b][384] (ch 0:128 | we 128:384)
__device__ float g_pre[2][SS][BB][1024];        // precomputed x-part + bias, unit-major float4
__device__ float g_out[SS * BB * 512];          // word BiLSTM output
__device__ float g_em[SS * BB * NT];            // emissions
__device__ float g_part[BB];                    // per-batch (num - den)

__device__ __forceinline__ float sigf(float x) { return 1.0f / (1.0f + expf(-x)); }
__device__ __forceinline__ void fma4(float4& a, const float4 w, float x) {
    a.x = fmaf(w.x, x, a.x); a.y = fmaf(w.y, x, a.y);
    a.z = fmaf(w.z, x, a.z); a.w = fmaf(w.w, x, a.w);
}

// ---------------- weight prep: permute to [k][unit][ifgo] ----------------
__global__ void k_prep_char(const float* __restrict__ wih_f, const float* __restrict__ whh_f,
                            const float* __restrict__ wih_b, const float* __restrict__ whh_b) {
    int id = blockIdx.x * 256 + threadIdx.x;          // 2*128*256 = 65536
    if (id >= 65536) return;
    int dir = id / 32768; int r = id % 32768;
    int k = r >> 8; int uq = r & 255; int u = uq >> 2; int q = uq & 3;
    const float* Wih = dir ? wih_b : wih_f;
    const float* Whh = dir ? whh_b : whh_f;
    int row = q * 64 + u;
    float v = (k < 64) ? Wih[row * 64 + k] : Whh[row * 64 + (k - 64)];
    g_cWP[dir][k][u][q] = v;
}

__global__ void k_prep_word(const float* __restrict__ wih_f, const float* __restrict__ whh_f,
                            const float* __restrict__ wih_b, const float* __restrict__ whh_b) {
    int id = blockIdx.x * 256 + threadIdx.x;          // 786432 + 524288
    if (id < 786432) {
        int dir = id / 393216; int r = id % 393216;
        int k = r >> 10; int uq = r & 1023; int u = uq >> 2; int q = uq & 3;
        const float* W = dir ? wih_b : wih_f;
        g_WIP[dir][k][u][q] = W[(q * 256 + u) * 384 + k];
    } else if (id < 786432 + 524288) {
        int r2 = id - 786432;
        int dir = r2 / 262144; int r = r2 % 262144;
        int k = r >> 10; int uq = r & 1023; int u = uq >> 2; int q = uq & 3;
        const float* W = dir ? whh_b : whh_f;
        g_WHP[dir][k][u][q] = W[(q * 256 + u) * 256 + k];
    }
}

// ---------------- word embedding gather into g_x[.., 128:384] ----------------
__global__ void k_gather(const int* __restrict__ sent, const float* __restrict__ Wwe) {
    int id = blockIdx.x * 256 + threadIdx.x;          // 4096 words * 64 float4
    if (id >= 4096 * 64) return;
    int word = id >> 6;                               // word = s*B + b (same order as sentence)
    int k4 = id & 63;
    int idx = sent[word];
    float4 v = ((const float4*)Wwe)[idx * 64 + k4];
    ((float4*)g_x)[word * 96 + 32 + k4] = v;
}

// ---------------- char BiLSTM (final hidden only) ----------------
// grid (128, 2dirs), 256 threads = 8 warps, each warp owns 4 words for all 16 steps.
__global__ __launch_bounds__(256) void k_char(const int* __restrict__ charArr,
                                              const float* __restrict__ Wce,
                                              const float* __restrict__ cb_f,
                                              const float* __restrict__ cb_b) {
    extern __shared__ float sm[];
    float* sW = sm;                       // [128][64][4] = 32768 floats
    float* sCE = sm + 32768;              // [100][64]    = 6400
    float* sXH = sm + 39168;              // [8 warps][4 words][128]
    int* sIdx = (int*)(sm + 43264);       // [8][4][16]

    int dir = blockIdx.y;
    int tid = threadIdx.x, warp = tid >> 5, lane = tid & 31;

    const float4* gw = ((const float4*)g_cWP) + dir * (128 * 64);
    float4* sW4 = (float4*)sW;
    for (int i = tid; i < 128 * 64; i += 256) sW4[i] = gw[i];
    for (int i = tid; i < 6400; i += 256) sCE[i] = Wce[i];

    int wordBase = blockIdx.x * 32 + warp * 4;
    for (int i = lane; i < 64; i += 32) {
        int wd = i >> 4, c = i & 15;
        sIdx[warp * 64 + i] = charArr[(wordBase + wd) * CC + c];
    }
    float* xh = sXH + warp * 512;         // [4][128]
    #pragma unroll
    for (int wd = 0; wd < 4; wd++) { xh[wd * 128 + 64 + lane] = 0.f; xh[wd * 128 + 96 + lane] = 0.f; }

    const float* cb = dir ? cb_b : cb_f;
    int lB = lane + 32;
    float4 bA = make_float4(cb[lane], cb[64 + lane], cb[128 + lane], cb[192 + lane]);
    float4 bB = make_float4(cb[lB], cb[64 + lB], cb[128 + lB], cb[192 + lB]);
    __syncthreads();

    float cAx[4] = {0, 0, 0, 0}, cBx[4] = {0, 0, 0, 0};

    for (int t = 0; t < 16; t++) {
        int cidx = dir ? (15 - t) : t;
        #pragma unroll
        for (int wd = 0; wd < 4; wd++) {
            int idx = sIdx[warp * 64 + wd * 16 + cidx];
            xh[wd * 128 + lane] = sCE[idx * 64 + lane];
            xh[wd * 128 + 32 + lane] = sCE[idx * 64 + 32 + lane];
        }
        __syncwarp();
        float4 aA[4], aB[4];
        #pragma unroll
        for (int wd = 0; wd < 4; wd++) { aA[wd] = bA; aB[wd] = bB; }
        #pragma unroll 4
        for (int k = 0; k < 128; k++) {
            float4 wA = sW4[k * 64 + lane];
            float4 wB = sW4[k * 64 + lane + 32];
            #pragma unroll
            for (int wd = 0; wd < 4; wd++) {
                float xv = xh[wd * 128 + k];
                fma4(aA[wd], wA, xv);
                fma4(aB[wd], wB, xv);
            }
        }
        __syncwarp();   // everyone done reading old h before overwrite
        #pragma unroll
        for (int wd = 0; wd < 4; wd++) {
            cAx[wd] = sigf(aA[wd].y) * cAx[wd] + sigf(aA[wd].x) * tanhf(aA[wd].z);
            float hA = sigf(aA[wd].w) * tanhf(cAx[wd]);
            cBx[wd] = sigf(aB[wd].y) * cBx[wd] + sigf(aB[wd].x) * tanhf(aB[wd].z);
            float hB = sigf(aB[wd].w) * tanhf(cBx[wd]);
            xh[wd * 128 + 64 + lane] = hA;
            xh[wd * 128 + 96 + lane] = hB;
        }
        __syncwarp();
    }
    // final h -> g_x[s][b][dir*64 + unit];  word n = b*S + s
    #pragma unroll
    for (int wd = 0; wd < 4; wd++) {
        int n = wordBase + wd;
        int b = n >> 7, s = n & 127;
        float* dst = g_x + (s * BB + b) * 384 + dir * 64;
        dst[lane] = xh[wd * 128 + 64 + lane];
        dst[32 + lane] = xh[wd * 128 + 96 + lane];
    }
}

// ---------------- x-part GEMM: pre = x @ Wih^T + b ----------------
// grid (S, 2dirs, 2 batch-halves), 256 threads: thread=unit, 4 gates x 16 batches
__global__ __launch_bounds__(256) void k_pre(const float* __restrict__ wb_f,
                                             const float* __restrict__ wb_b) {
    __shared__ float sx[16][384];
    int s = blockIdx.x, dir = blockIdx.y, bh = blockIdx.z;
    int u = threadIdx.x;
    const float* xsrc = g_x + (s * BB + bh * 16) * 384;
    for (int i = u; i < 16 * 384; i += 256) sx[i / 384][i % 384] = xsrc[i];
    __syncthreads();

    const float* wb = dir ? wb_b : wb_f;
    float4 bias = make_float4(wb[u], wb[256 + u], wb[512 + u], wb[768 + u]);
    float4 acc[16];
    #pragma unroll
    for (int b = 0; b < 16; b++) acc[b] = bias;

    const float4* W = ((const float4*)g_WIP) + dir * (384 * 256);
    #pragma unroll 2
    for (int k = 0; k < 384; k++) {
        float4 w = W[k * 256 + u];
        #pragma unroll
        for (int b = 0; b < 16; b++) fma4(acc[b], w, sx[b][k]);
    }
    float4* dst = ((float4*)g_pre) + (((dir * SS + s) * BB) + bh * 16) * 256;
    #pragma unroll
    for (int b = 0; b < 16; b++) dst[b * 256 + u] = acc[b];
}

// ---------------- word LSTM recurrence ----------------
// grid 32 = (dir, batch-pair); block 256 threads = 256 hidden units (4 gates each via float4)
__global__ __launch_bounds__(256) void k_rec() {
    __shared__ float h0b[256], h1b[256];
    int bxi = blockIdx.x;
    int dir = bxi & 1, pair = bxi >> 1;
    int u = threadIdx.x;
    int b0 = pair * 2, b1 = b0 + 1;
    h0b[u] = 0.f; h1b[u] = 0.f;
    float c0 = 0.f, c1 = 0.f;
    const float4* W = ((const float4*)g_WHP) + dir * (256 * 256);
    const float4* pre = ((const float4*)g_pre) + dir * (SS * BB * 256);
    __syncthreads();

    for (int t = 0; t < SS; t++) {
        int s = dir ? (SS - 1 - t) : t;
        float4 a0 = pre[(s * BB + b0) * 256 + u];
        float4 a1 = pre[(s * BB + b1) * 256 + u];
        #pragma unroll 4
        for (int k = 0; k < 256; k++) {
            float4 w = W[k * 256 + u];
            float hh0 = h0b[k], hh1 = h1b[k];
            fma4(a0, w, hh0);
            fma4(a1, w, hh1);
        }
        c0 = sigf(a0.y) * c0 + sigf(a0.x) * tanhf(a0.z);
        float nh0 = sigf(a0.w) * tanhf(c0);
        c1 = sigf(a1.y) * c1 + sigf(a1.x) * tanhf(a1.z);
        float nh1 = sigf(a1.w) * tanhf(c1);
        __syncthreads();            // all reads of old h done
        h0b[u] = nh0; h1b[u] = nh1;
        float* o = g_out + (s * BB) * 512 + dir * 256 + u;
        o[b0 * 512] = nh0;
        o[b1 * 512] = nh1;
        __syncthreads();            // new h visible
    }
}

// ---------------- emissions: em = out @ emit_W^T + emit_b ----------------
__global__ __launch_bounds__(544) void k_em(const float* __restrict__ emW,
                                            const float* __restrict__ emb) {
    extern __shared__ float sm[];
    float* sO = sm;                // [32][513]
    float* sE = sm + 32 * 513;     // [17][513]
    int s = blockIdx.x, tid = threadIdx.x;
    const float* osrc = g_out + s * BB * 512;
    for (int i = tid; i < 32 * 512; i += 544) sO[(i >> 9) * 513 + (i & 511)] = osrc[i];
    for (int i = tid; i < 17 * 512; i += 544) sE[(i / 512) * 513 + (i % 512)] = emW[i];
    __syncthreads();
    int b = tid / 17, j = tid % 17;
    const float* ro = sO + b * 513;
    const float* rw = sE + j * 513;
    float acc = emb[j];
    #pragma unroll 8
    for (int k = 0; k < 512; k++) acc = fmaf(ro[k], rw[k], acc);
    g_em[(s * BB + b) * NT + j] = acc;
}

// ---------------- CRF: per-batch num & den ----------------
__global__ void k_crf(const int* __restrict__ tags, const float* __restrict__ trans,
                      const float* __restrict__ startv, const float* __restrict__ endv) {
    __shared__ float sE[NT][18], sT[NT][18], sU[32];
    int b = blockIdx.x, lane = threadIdx.x;
    for (int i = lane; i < NT * NT; i += 32) {
        float v = trans[i];
        sT[i / NT][i % NT] = v;
        sE[i / NT][i % NT] = expf(v);
    }
    __syncwarp();
    float alpha = -1e30f;
    if (lane < NT) alpha = startv[lane] + g_em[b * NT + lane];
    for (int t = 1; t < SS; t++) {
        float m = alpha;
        #pragma unroll
        for (int o = 16; o > 0; o >>= 1) m = fmaxf(m, __shfl_xor_sync(0xffffffffu, m, o));
        float uu = expf(alpha - m);            // lanes >= 17 -> 0
        sU[lane] = uu;
        __syncwarp();
        if (lane < NT) {
            float ssum = 0.f;
            #pragma unroll
            for (int i = 0; i < NT; i++) ssum = fmaf(sU[i], sE[i][lane], ssum);
            alpha = m + logf(ssum) + g_em[(t * BB + b) * NT + lane];
        }
        __syncwarp();
    }
    float v = (lane < NT) ? (alpha + endv[lane]) : -1e30f;
    float m2 = v;
    #pragma unroll
    for (int o = 16; o > 0; o >>= 1) m2 = fmaxf(m2, __shfl_xor_sync(0xffffffffu, m2, o));
    float e2 = expf(v - m2);
    #pragma unroll
    for (int o = 16; o > 0; o >>= 1) e2 += __shfl_xor_sync(0xffffffffu, e2, o);
    float den = m2 + logf(e2);

    // numerator (mask is always true: sentence ids >= 2)
    float part = 0.f;
    for (int t = lane; t < SS; t += 32) {
        int tg = tags[t * BB + b];
        part += g_em[(t * BB + b) * NT + tg];
        if (t > 0) {
            int tp = tags[(t - 1) * BB + b];
            part += sT[tp][tg];
        }
    }
    #pragma unroll
    for (int o = 16; o > 0; o >>= 1) part += __shfl_xor_sync(0xffffffffu, part, o);
    if (lane == 0) {
        int t0 = tags[b];
        int tl = tags[(SS - 1) * BB + b];
        float num = part + startv[t0] + endv[tl];
        g_part[b] = num - den;
    }
}

__global__ void k_final(float* out) {
    int lane = threadIdx.x;
    float v = g_part[lane];
    #pragma unroll
    for (int o = 16; o > 0; o >>= 1) v += __shfl_xor_sync(0xffffffffu, v, o);
    if (lane == 0) out[0] = -v;
}

// ---------------- launch ----------------
extern "C" void kernel_launch(void* const* d_in, const int* in_sizes, int n_in,
                              void* d_out, int out_size) {
    const int* sent = (const int*)d_in[0];
    const int* ch   = (const int*)d_in[1];
    const int* tags = (const int*)d_in[2];
    const float* Wwe = (const float*)d_in[3];
    const float* Wce = (const float*)d_in[4];
    const float* c_Wih_f = (const float*)d_in[5];
    const float* c_Whh_f = (const float*)d_in[6];
    const float* c_b_f   = (const float*)d_in[7];
    const float* c_Wih_b = (const float*)d_in[8];
    const float* c_Whh_b = (const float*)d_in[9];
    const float* c_b_b   = (const float*)d_in[10];
    const float* w_Wih_f = (const float*)d_in[11];
    const float* w_Whh_f = (const float*)d_in[12];
    const float* w_b_f   = (const float*)d_in[13];
    const float* w_Wih_b = (const float*)d_in[14];
    const float* w_Whh_b = (const float*)d_in[15];
    const float* w_b_b   = (const float*)d_in[16];
    const float* emW  = (const float*)d_in[17];
    const float* emb  = (const float*)d_in[18];
    const float* trans  = (const float*)d_in[19];
    const float* startv = (const float*)d_in[20];
    const float* endv   = (const float*)d_in[21];

    const int CHAR_SMEM = 175104;                     // 43776 floats
    const int EM_SMEM = (32 * 513 + 17 * 513) * 4;    // 100548 B
    cudaFuncSetAttribute(k_char, cudaFuncAttributeMaxDynamicSharedMemorySize, CHAR_SMEM);
    cudaFuncSetAttribute(k_em, cudaFuncAttributeMaxDynamicSharedMemorySize, EM_SMEM);

    k_prep_char<<<256, 256>>>(c_Wih_f, c_Whh_f, c_Wih_b, c_Whh_b);
    k_prep_word<<<5120, 256>>>(w_Wih_f, w_Whh_f, w_Wih_b, w_Whh_b);
    k_gather<<<1024, 256>>>(sent, Wwe);
    k_char<<<dim3(128, 2), 256, CHAR_SMEM>>>(ch, Wce, c_b_f, c_b_b);
    k_pre<<<dim3(128, 2, 2), 256>>>(w_b_f, w_b_b);
    k_rec<<<32, 256>>>();
    k_em<<<128, 544, EM_SMEM>>>(emW, emb);
    k_crf<<<32, 32>>>(tags, trans, startv, endv);
    k_final<<<1, 32>>>((float*)d_out);
}

// round 11
// speedup vs baseline: 2.3250x; 2.3250x over previous
#include <cuda_runtime.h>
#include <cuda_bf16.h>
#include <math.h>

// Problem constants
#define SS 128   // sequence length
#define BB 32    // batch
#define CC 16    // chars per word
#define DW 256   // word emb dim
#define DC 64    // char emb dim
#define HC2 64   // char hidden per dir
#define HW2 256  // word hidden per dir
#define NT 17    // tags

// ---------------- scratch (static device memory; no allocations) ----------------
__device__ float g_cWP[2][128][64][4];          // char weights permuted [dir][k][unit][ifgo]
__device__ float g_WIP[2][384][256][4];         // word Wih permuted    [dir][k][unit][ifgo]
__device__ float g_WHP[2][256][256][4];         // word Whh permuted    [dir][k][unit][ifgo]
__device__ float g_x[SS * BB * 384];            // word-LSTM input  [s][b][384] (ch 0:128 | we 128:384)
__device__ float g_pre[2][SS][BB][1024];        // precomputed x-part + bias, unit-major float4
__device__ float g_out[SS * BB * 512];          // word BiLSTM output
__device__ float g_em[SS * BB * NT];            // emissions
__device__ float g_part[BB];                    // per-batch (num - den)

__device__ __forceinline__ float sigf(float x) { return 1.0f / (1.0f + expf(-x)); }

// ---- packed f32x2 helpers (FFMA2 path on sm_103a) ----
__device__ __forceinline__ unsigned long long pk2(float a, float b) {
    unsigned long long r;
    asm("mov.b64 %0, {%1, %2};" : "=l"(r) : "r"(__float_as_uint(a)), "r"(__float_as_uint(b)));
    return r;
}
__device__ __forceinline__ void upk2(unsigned long long v, float& a, float& b) {
    unsigned int x, y;
    asm("mov.b64 {%0, %1}, %2;" : "=r"(x), "=r"(y) : "l"(v));
    a = __uint_as_float(x); b = __uint_as_float(y);
}
__device__ __forceinline__ unsigned long long fma2(unsigned long long a, unsigned long long b,
                                                   unsigned long long c) {
    unsigned long long d;
    asm("fma.rn.f32x2 %0, %1, %2, %3;" : "=l"(d) : "l"(a), "l"(b), "l"(c));
    return d;
}
__device__ __forceinline__ unsigned long long add2(unsigned long long a, unsigned long long b) {
    unsigned long long d;
    asm("add.rn.f32x2 %0, %1, %2;" : "=l"(d) : "l"(a), "l"(b));
    return d;
}
__device__ __forceinline__ unsigned int smem_u32(const void* p) {
    unsigned int a;
    asm("{ .reg .u64 t; cvta.to.shared.u64 t, %1; cvt.u32.u64 %0, t; }" : "=r"(a) : "l"(p));
    return a;
}
#define CLUSTER_SYNC_() do {                                          \
    asm volatile("barrier.cluster.arrive.aligned;" ::: "memory");     \
    asm volatile("barrier.cluster.wait.aligned;" ::: "memory");       \
} while (0)

// ---------------- weight prep: permute to [k][unit][ifgo] ----------------
__global__ void k_prep_char(const float* __restrict__ wih_f, const float* __restrict__ whh_f,
                            const float* __restrict__ wih_b, const float* __restrict__ whh_b) {
    int id = blockIdx.x * 256 + threadIdx.x;          // 2*128*256 = 65536
    if (id >= 65536) return;
    int dir = id / 32768; int r = id % 32768;
    int k = r >> 8; int uq = r & 255; int u = uq >> 2; int q = uq & 3;
    const float* Wih = dir ? wih_b : wih_f;
    const float* Whh = dir ? whh_b : whh_f;
    int row = q * 64 + u;
    float v = (k < 64) ? Wih[row * 64 + k] : Whh[row * 64 + (k - 64)];
    g_cWP[dir][k][u][q] = v;
}

__global__ void k_prep_word(const float* __restrict__ wih_f, const float* __restrict__ whh_f,
                            const float* __restrict__ wih_b, const float* __restrict__ whh_b) {
    int id = blockIdx.x * 256 + threadIdx.x;          // 786432 + 524288
    if (id < 786432) {
        int dir = id / 393216; int r = id % 393216;
        int k = r >> 10; int uq = r & 1023; int u = uq >> 2; int q = uq & 3;
        const float* W = dir ? wih_b : wih_f;
        g_WIP[dir][k][u][q] = W[(q * 256 + u) * 384 + k];
    } else if (id < 786432 + 524288) {
        int r2 = id - 786432;
        int dir = r2 / 262144; int r = r2 % 262144;
        int k = r >> 10; int uq = r & 1023; int u = uq >> 2; int q = uq & 3;
        const float* W = dir ? whh_b : whh_f;
        g_WHP[dir][k][u][q] = W[(q * 256 + u) * 256 + k];
    }
}

// ---------------- word embedding gather into g_x[.., 128:384] ----------------
__global__ void k_gather(const int* __restrict__ sent, const float* __restrict__ Wwe) {
    int id = blockIdx.x * 256 + threadIdx.x;          // 4096 words * 64 float4
    if (id >= 4096 * 64) return;
    int word = id >> 6;
    int k4 = id & 63;
    int idx = sent[word];
    float4 v = ((const float4*)Wwe)[idx * 64 + k4];
    ((float4*)g_x)[word * 96 + 32 + k4] = v;
}

// ---------------- char BiLSTM (final hidden only), FFMA2 ----------------
// grid (128, 2dirs), 256 threads = 8 warps, each warp owns 4 words for all 16 steps.
// smem: sW (ulonglong2[128][64]) 128KB | sCE 25600B | xh2 (u64[8][4][128]) 32768B | sIdx 2048B
#define CHAR_SMEM (131072 + 25600 + 32768 + 2048)
__global__ __launch_bounds__(256) void k_char(const int* __restrict__ charArr,
                                              const float* __restrict__ Wce,
                                              const float* __restrict__ cb_f,
                                              const float* __restrict__ cb_b) {
    extern __shared__ float sm[];
    ulonglong2* sW = (ulonglong2*)sm;                               // [128][64]
    float* sCE = sm + 32768;                                        // 6400 floats
    unsigned long long* sXH = (unsigned long long*)(sm + 39168);    // [8][4][128] u64
    int* sIdx = (int*)(sm + 39168 + 8192);                          // [8][4][16]

    int dir = blockIdx.y;
    int tid = threadIdx.x, warp = tid >> 5, lane = tid & 31;

    const float4* gw = ((const float4*)g_cWP) + dir * (128 * 64);
    float4* sW4 = (float4*)sW;
    for (int i = tid; i < 128 * 64; i += 256) sW4[i] = gw[i];
    for (int i = tid; i < 6400; i += 256) sCE[i] = Wce[i];

    int wordBase = blockIdx.x * 32 + warp * 4;
    for (int i = lane; i < 64; i += 32) {
        int wd = i >> 4, c = i & 15;
        sIdx[warp * 64 + i] = charArr[(wordBase + wd) * CC + c];
    }
    unsigned long long* xh = sXH + warp * 512;         // [4][128]
    #pragma unroll
    for (int wd = 0; wd < 4; wd++) { xh[wd * 128 + 64 + lane] = 0ull; xh[wd * 128 + 96 + lane] = 0ull; }

    const float* cb = dir ? cb_b : cb_f;
    int lB = lane + 32;
    unsigned long long bA01 = pk2(cb[lane], cb[64 + lane]);
    unsigned long long bA23 = pk2(cb[128 + lane], cb[192 + lane]);
    unsigned long long bB01 = pk2(cb[lB], cb[64 + lB]);
    unsigned long long bB23 = pk2(cb[128 + lB], cb[192 + lB]);
    __syncthreads();

    float cAx[4] = {0, 0, 0, 0}, cBx[4] = {0, 0, 0, 0};

    for (int t = 0; t < 16; t++) {
        int cidx = dir ? (15 - t) : t;
        #pragma unroll
        for (int wd = 0; wd < 4; wd++) {
            int idx = sIdx[warp * 64 + wd * 16 + cidx];
            float e0 = sCE[idx * 64 + lane];
            float e1 = sCE[idx * 64 + 32 + lane];
            xh[wd * 128 + lane] = pk2(e0, e0);
            xh[wd * 128 + 32 + lane] = pk2(e1, e1);
        }
        __syncwarp();
        unsigned long long aA01[4], aA23[4], aB01[4], aB23[4];
        #pragma unroll
        for (int wd = 0; wd < 4; wd++) {
            aA01[wd] = bA01; aA23[wd] = bA23; aB01[wd] = bB01; aB23[wd] = bB23;
        }
        #pragma unroll 2
        for (int k = 0; k < 128; k++) {
            ulonglong2 wA = sW[k * 64 + lane];
            ulonglong2 wB = sW[k * 64 + lane + 32];
            #pragma unroll
            for (int wd = 0; wd < 4; wd++) {
                unsigned long long xv = xh[wd * 128 + k];
                aA01[wd] = fma2(wA.x, xv, aA01[wd]);
                aA23[wd] = fma2(wA.y, xv, aA23[wd]);
                aB01[wd] = fma2(wB.x, xv, aB01[wd]);
                aB23[wd] = fma2(wB.y, xv, aB23[wd]);
            }
        }
        __syncwarp();   // everyone done reading old h before overwrite
        #pragma unroll
        for (int wd = 0; wd < 4; wd++) {
            float iA, fA, gA, oA, iB, fB, gB, oB;
            upk2(aA01[wd], iA, fA); upk2(aA23[wd], gA, oA);
            upk2(aB01[wd], iB, fB); upk2(aB23[wd], gB, oB);
            cAx[wd] = sigf(fA) * cAx[wd] + sigf(iA) * tanhf(gA);
            float hA = sigf(oA) * tanhf(cAx[wd]);
            cBx[wd] = sigf(fB) * cBx[wd] + sigf(iB) * tanhf(gB);
            float hB = sigf(oB) * tanhf(cBx[wd]);
            xh[wd * 128 + 64 + lane] = pk2(hA, hA);
            xh[wd * 128 + 96 + lane] = pk2(hB, hB);
        }
        __syncwarp();
    }
    // final h -> g_x[s][b][dir*64 + unit];  word n = b*S + s
    #pragma unroll
    for (int wd = 0; wd < 4; wd++) {
        int n = wordBase + wd;
        int b = n >> 7, s = n & 127;
        float* dst = g_x + (s * BB + b) * 384 + dir * 64;
        float hA, hB, dummy;
        upk2(xh[wd * 128 + 64 + lane], hA, dummy);
        upk2(xh[wd * 128 + 96 + lane], hB, dummy);
        dst[lane] = hA;
        dst[32 + lane] = hB;
    }
}

// ---------------- x-part GEMM (FFMA2, batch-pair packed): pre = x @ Wih^T + b ----------------
// grid (S, 2dirs, 2 batch-halves), 256 threads: thread = unit; 8 batch-pairs x 4 gates
__global__ __launch_bounds__(256) void k_pre(const float* __restrict__ wb_f,
                                             const float* __restrict__ wb_b) {
    __shared__ unsigned long long sxp[8][384];   // {x[b], x[b+8]} per k
    int s = blockIdx.x, dir = blockIdx.y, bh = blockIdx.z;
    int u = threadIdx.x;
    const float* xsrc = g_x + (s * BB + bh * 16) * 384;
    for (int i = u; i < 8 * 384; i += 256) {
        int b2 = i / 384, k = i % 384;
        sxp[b2][k] = pk2(xsrc[b2 * 384 + k], xsrc[(b2 + 8) * 384 + k]);
    }
    __syncthreads();

    unsigned long long a0[8], a1[8], a2[8], a3[8];
    #pragma unroll
    for (int p = 0; p < 8; p++) { a0[p] = 0ull; a1[p] = 0ull; a2[p] = 0ull; a3[p] = 0ull; }

    const float4* W = ((const float4*)g_WIP) + dir * (384 * 256);
    #pragma unroll 2
    for (int k = 0; k < 384; k++) {
        float4 w = W[k * 256 + u];
        unsigned long long w0 = pk2(w.x, w.x), w1 = pk2(w.y, w.y);
        unsigned long long w2 = pk2(w.z, w.z), w3 = pk2(w.w, w.w);
        #pragma unroll
        for (int p = 0; p < 8; p++) {
            unsigned long long xv = sxp[p][k];
            a0[p] = fma2(w0, xv, a0[p]);
            a1[p] = fma2(w1, xv, a1[p]);
            a2[p] = fma2(w2, xv, a2[p]);
            a3[p] = fma2(w3, xv, a3[p]);
        }
    }
    const float* wb = dir ? wb_b : wb_f;
    float bi = wb[u], bf = wb[256 + u], bg = wb[512 + u], bo = wb[768 + u];
    float4* dst = ((float4*)g_pre) + (((dir * SS + s) * BB) + bh * 16) * 256;
    #pragma unroll
    for (int p = 0; p < 8; p++) {
        float x0, y0, x1, y1, x2, y2, x3, y3;
        upk2(a0[p], x0, y0); upk2(a1[p], x1, y1);
        upk2(a2[p], x2, y2); upk2(a3[p], x3, y3);
        dst[p * 256 + u]       = make_float4(x0 + bi, x1 + bf, x2 + bg, x3 + bo);
        dst[(p + 8) * 256 + u] = make_float4(y0 + bi, y1 + bf, y2 + bg, y3 + bo);
    }
}

// ---------------- word LSTM recurrence: 8-CTA cluster, SMEM-resident Whh ----------------
// 16 clusters (dir x 8 batch-groups) x 8 CTAs; CTA rank owns units [rank*32, rank*32+32).
// 128 threads: thread = (u_loc = tid>>2, bl = tid&3). h exchanged via DSMEM, double-buffered.
#define REC_SMEM (131072 + 16384)   // sW [256][32] ulonglong2 (128KB) + h2 [2][4][256] u64 (16KB)
__global__ __launch_bounds__(128, 1) __cluster_dims__(8, 1, 1) void k_rec2() {
    extern __shared__ float smr[];
    ulonglong2* sW = (ulonglong2*)smr;                               // [k=256][u_loc=32]
    unsigned long long* h2 = (unsigned long long*)(smr + 32768);     // [2][4][256] {h,h}

    int cta = blockIdx.x;
    int rank = cta & 7, cid = cta >> 3;
    int dir = cid & 1, bg = cid >> 1;
    int tid = threadIdx.x;
    int u = tid >> 2, bl = tid & 3;
    int uG = rank * 32 + u;
    int bG = bg * 4 + bl;

    // load Whh slice: [k][uG] float4 == ulonglong2 {(i,f),(g,o)}
    const float4* g4 = ((const float4*)g_WHP) + dir * 65536;
    float4* sW4 = (float4*)sW;
    for (int i = tid; i < 8192; i += 128) {
        int k = i >> 5, uu = i & 31;
        sW4[i] = g4[k * 256 + rank * 32 + uu];
    }
    // zero own h buffer 0
    for (int i = tid; i < 1024; i += 128) h2[i] = 0ull;
    __syncthreads();
    CLUSTER_SYNC_();

    unsigned int h2_sa = smem_u32(h2);
    const ulonglong2* pre2 = (const ulonglong2*)g_pre;
    float c = 0.f;
    int cur = 0;

    for (int t = 0; t < SS; t++) {
        int s = dir ? (SS - 1 - t) : t;
        ulonglong2 av = pre2[(size_t)((dir * SS + s) * BB + bG) * 256 + uG];
        unsigned long long a01 = av.x, a23 = av.y;      // even chain (seeded with pre)
        unsigned long long b01 = 0ull, b23 = 0ull;      // odd chain
        const unsigned long long* hb = h2 + cur * 1024 + bl * 256;
        #pragma unroll 8
        for (int k = 0; k < 256; k += 2) {
            ulonglong2 w0 = sW[k * 32 + u];
            ulonglong2 w1 = sW[(k + 1) * 32 + u];
            unsigned long long h0 = hb[k];
            unsigned long long h1 = hb[k + 1];
            a01 = fma2(w0.x, h0, a01);
            a23 = fma2(w0.y, h0, a23);
            b01 = fma2(w1.x, h1, b01);
            b23 = fma2(w1.y, h1, b23);
        }
        a01 = add2(a01, b01);
        a23 = add2(a23, b23);
        float gi, gf, gg, go;
        upk2(a01, gi, gf); upk2(a23, gg, go);
        c = sigf(gf) * c + sigf(gi) * tanhf(gg);
        float h = sigf(go) * tanhf(c);

        int nxt = cur ^ 1;
        unsigned long long hp = pk2(h, h);
        unsigned int off = h2_sa + (unsigned)((nxt * 1024 + bl * 256 + uG) * 8);
        #pragma unroll
        for (int r = 0; r < 8; r++) {
            unsigned int ra;
            asm volatile("mapa.shared::cluster.u32 %0, %1, %2;" : "=r"(ra) : "r"(off), "r"(r));
            asm volatile("st.shared::cluster.b64 [%0], %1;" :: "r"(ra), "l"(hp) : "memory");
        }
        g_out[(s * BB + bG) * 512 + dir * 256 + uG] = h;
        CLUSTER_SYNC_();            // release/acquire: h(t+1) visible cluster-wide
        cur = nxt;
    }
}

// ---------------- emissions: em = out @ emit_W^T + emit_b ----------------
__global__ __launch_bounds__(544) void k_em(const float* __restrict__ emW,
                                            const float* __restrict__ emb) {
    extern __shared__ float sm[];
    float* sO = sm;                // [32][513]
    float* sE = sm + 32 * 513;     // [17][513]
    int s = blockIdx.x, tid = threadIdx.x;
    const float* osrc = g_out + s * BB * 512;
    for (int i = tid; i < 32 * 512; i += 544) sO[(i >> 9) * 513 + (i & 511)] = osrc[i];
    for (int i = tid; i < 17 * 512; i += 544) sE[(i / 512) * 513 + (i % 512)] = emW[i];
    __syncthreads();
    int b = tid / 17, j = tid % 17;
    const float* ro = sO + b * 513;
    const float* rw = sE + j * 513;
    float acc = emb[j];
    #pragma unroll 8
    for (int k = 0; k < 512; k++) acc = fmaf(ro[k], rw[k], acc);
    g_em[(s * BB + b) * NT + j] = acc;
}

// ---------------- CRF: per-batch num & den ----------------
__global__ void k_crf(const int* __restrict__ tags, const float* __restrict__ trans,
                      const float* __restrict__ startv, const float* __restrict__ endv) {
    __shared__ float sE[NT][18], sT[NT][18], sU[32];
    int b = blockIdx.x, lane = threadIdx.x;
    for (int i = lane; i < NT * NT; i += 32) {
        float v = trans[i];
        sT[i / NT][i % NT] = v;
        sE[i / NT][i % NT] = expf(v);
    }
    __syncwarp();
    float alpha = -1e30f;
    if (lane < NT) alpha = startv[lane] + g_em[b * NT + lane];
    for (int t = 1; t < SS; t++) {
        float m = alpha;
        #pragma unroll
        for (int o = 16; o > 0; o >>= 1) m = fmaxf(m, __shfl_xor_sync(0xffffffffu, m, o));
        float uu = expf(alpha - m);            // lanes >= 17 -> 0
        sU[lane] = uu;
        __syncwarp();
        if (lane < NT) {
            float ssum = 0.f;
            #pragma unroll
            for (int i = 0; i < NT; i++) ssum = fmaf(sU[i], sE[i][lane], ssum);
            alpha = m + logf(ssum) + g_em[(t * BB + b) * NT + lane];
        }
        __syncwarp();
    }
    float v = (lane < NT) ? (alpha + endv[lane]) : -1e30f;
    float m2 = v;
    #pragma unroll
    for (int o = 16; o > 0; o >>= 1) m2 = fmaxf(m2, __shfl_xor_sync(0xffffffffu, m2, o));
    float e2 = expf(v - m2);
    #pragma unroll
    for (int o = 16; o > 0; o >>= 1) e2 += __shfl_xor_sync(0xffffffffu, e2, o);
    float den = m2 + logf(e2);

    // numerator (mask always true: sentence ids >= 2)
    float part = 0.f;
    for (int t = lane; t < SS; t += 32) {
        int tg = tags[t * BB + b];
        part += g_em[(t * BB + b) * NT + tg];
        if (t > 0) {
            int tp = tags[(t - 1) * BB + b];
            part += sT[tp][tg];
        }
    }
    #pragma unroll
    for (int o = 16; o > 0; o >>= 1) part += __shfl_xor_sync(0xffffffffu, part, o);
    if (lane == 0) {
        int t0 = tags[b];
        int tl = tags[(SS - 1) * BB + b];
        float num = part + startv[t0] + endv[tl];
        g_part[b] = num - den;
    }
}

__global__ void k_final(float* out) {
    int lane = threadIdx.x;
    float v = g_part[lane];
    #pragma unroll
    for (int o = 16; o > 0; o >>= 1) v += __shfl_xor_sync(0xffffffffu, v, o);
    if (lane == 0) out[0] = -v;
}

// ---------------- launch ----------------
extern "C" void kernel_launch(void* const* d_in, const int* in_sizes, int n_in,
                              void* d_out, int out_size) {
    const int* sent = (const int*)d_in[0];
    const int* ch   = (const int*)d_in[1];
    const int* tags = (const int*)d_in[2];
    const float* Wwe = (const float*)d_in[3];
    const float* Wce = (const float*)d_in[4];
    const float* c_Wih_f = (const float*)d_in[5];
    const float* c_Whh_f = (const float*)d_in[6];
    const float* c_b_f   = (const float*)d_in[7];
    const float* c_Wih_b = (const float*)d_in[8];
    const float* c_Whh_b = (const float*)d_in[9];
    const float* c_b_b   = (const float*)d_in[10];
    const float* w_Wih_f = (const float*)d_in[11];
    const float* w_Whh_f = (const float*)d_in[12];
    const float* w_b_f   = (const float*)d_in[13];
    const float* w_Wih_b = (const float*)d_in[14];
    const float* w_Whh_b = (const float*)d_in[15];
    const float* w_b_b   = (const float*)d_in[16];
    const float* emW  = (const float*)d_in[17];
    const float* emb  = (const float*)d_in[18];
    const float* trans  = (const float*)d_in[19];
    const float* startv = (const float*)d_in[20];
    const float* endv   = (const float*)d_in[21];

    const int EM_SMEM = (32 * 513 + 17 * 513) * 4;
    cudaFuncSetAttribute(k_char, cudaFuncAttributeMaxDynamicSharedMemorySize, CHAR_SMEM);
    cudaFuncSetAttribute(k_rec2, cudaFuncAttributeMaxDynamicSharedMemorySize, REC_SMEM);
    cudaFuncSetAttribute(k_em, cudaFuncAttributeMaxDynamicSharedMemorySize, EM_SMEM);

    k_prep_char<<<256, 256>>>(c_Wih_f, c_Whh_f, c_Wih_b, c_Whh_b);
    k_prep_word<<<5120, 256>>>(w_Wih_f, w_Whh_f, w_Wih_b, w_Whh_b);
    k_gather<<<1024, 256>>>(sent, Wwe);
    k_char<<<dim3(128, 2), 256, CHAR_SMEM>>>(ch, Wce, c_b_f, c_b_b);
    k_pre<<<dim3(128, 2, 2), 256>>>(w_b_f, w_b_b);
    k_rec2<<<128, 128, REC_SMEM>>>();
    k_em<<<128, 544, EM_SMEM>>>(emW, emb);
    k_crf<<<32, 32>>>(tags, trans, startv, endv);
    k_final<<<1, 32>>>((float*)d_out);
}

// round 12
// speedup vs baseline: 2.3283x; 1.0014x over previous
#include <cuda_runtime.h>
#include <cuda_bf16.h>
#include <math.h>

// Problem constants
#define SS 128   // sequence length
#define BB 32    // batch
#define CC 16    // chars per word
#define DW 256   // word emb dim
#define DC 64    // char emb dim
#define HC2 64   // char hidden per dir
#define HW2 256  // word hidden per dir
#define NT 17    // tags

// ---------------- scratch (static device memory; no allocations) ----------------
__device__ float g_cWP[2][128][64][4];          // char weights permuted [dir][k][unit][ifgo]
__device__ float g_WIP[2][384][256][4];         // word Wih permuted    [dir][k][unit][ifgo]
__device__ float g_WHP[2][256][256][4];         // word Whh permuted    [dir][k][unit][ifgo]
__device__ float g_x[SS * BB * 384];            // word-LSTM input  [s][b][384] (ch 0:128 | we 128:384)
__device__ float g_pre[2][SS][BB][1024];        // precomputed x-part + bias, unit-major float4
__device__ float g_out[SS * BB * 512];          // word BiLSTM output
__device__ float g_em[SS * BB * NT];            // emissions
__device__ float g_part[BB];                    // per-batch (num - den)

__device__ __forceinline__ float sigf(float x) { return 1.0f / (1.0f + expf(-x)); }

// ---- packed f32x2 helpers (FFMA2 path on sm_103a) ----
__device__ __forceinline__ unsigned long long pk2(float a, float b) {
    unsigned long long r;
    asm("mov.b64 %0, {%1, %2};" : "=l"(r) : "r"(__float_as_uint(a)), "r"(__float_as_uint(b)));
    return r;
}
__device__ __forceinline__ void upk2(unsigned long long v, float& a, float& b) {
    unsigned int x, y;
    asm("mov.b64 {%0, %1}, %2;" : "=r"(x), "=r"(y) : "l"(v));
    a = __uint_as_float(x); b = __uint_as_float(y);
}
__device__ __forceinline__ unsigned long long fma2(unsigned long long a, unsigned long long b,
                                                   unsigned long long c) {
    unsigned long long d;
    asm("fma.rn.f32x2 %0, %1, %2, %3;" : "=l"(d) : "l"(a), "l"(b), "l"(c));
    return d;
}
__device__ __forceinline__ unsigned long long add2(unsigned long long a, unsigned long long b) {
    unsigned long long d;
    asm("add.rn.f32x2 %0, %1, %2;" : "=l"(d) : "l"(a), "l"(b));
    return d;
}
__device__ __forceinline__ unsigned int smem_u32(const void* p) {
    unsigned int a;
    asm("{ .reg .u64 t; cvta.to.shared.u64 t, %1; cvt.u32.u64 %0, t; }" : "=r"(a) : "l"(p));
    return a;
}
#define CLUSTER_SYNC_() do {                                          \
    asm volatile("barrier.cluster.arrive.aligned;" ::: "memory");     \
    asm volatile("barrier.cluster.wait.aligned;" ::: "memory");       \
} while (0)

// ---------------- weight prep: permute to [k][unit][ifgo] ----------------
__global__ void k_prep_char(const float* __restrict__ wih_f, const float* __restrict__ whh_f,
                            const float* __restrict__ wih_b, const float* __restrict__ whh_b) {
    int id = blockIdx.x * 256 + threadIdx.x;          // 2*128*256 = 65536
    if (id >= 65536) return;
    int dir = id / 32768; int r = id % 32768;
    int k = r >> 8; int uq = r & 255; int u = uq >> 2; int q = uq & 3;
    const float* Wih = dir ? wih_b : wih_f;
    const float* Whh = dir ? whh_b : whh_f;
    int row = q * 64 + u;
    float v = (k < 64) ? Wih[row * 64 + k] : Whh[row * 64 + (k - 64)];
    g_cWP[dir][k][u][q] = v;
}

__global__ void k_prep_word(const float* __restrict__ wih_f, const float* __restrict__ whh_f,
                            const float* __restrict__ wih_b, const float* __restrict__ whh_b) {
    int id = blockIdx.x * 256 + threadIdx.x;          // 786432 + 524288
    if (id < 786432) {
        int dir = id / 393216; int r = id % 393216;
        int k = r >> 10; int uq = r & 1023; int u = uq >> 2; int q = uq & 3;
        const float* W = dir ? wih_b : wih_f;
        g_WIP[dir][k][u][q] = W[(q * 256 + u) * 384 + k];
    } else if (id < 786432 + 524288) {
        int r2 = id - 786432;
        int dir = r2 / 262144; int r = r2 % 262144;
        int k = r >> 10; int uq = r & 1023; int u = uq >> 2; int q = uq & 3;
        const float* W = dir ? whh_b : whh_f;
        g_WHP[dir][k][u][q] = W[(q * 256 + u) * 256 + k];
    }
}

// ---------------- word embedding gather into g_x[.., 128:384] ----------------
__global__ void k_gather(const int* __restrict__ sent, const float* __restrict__ Wwe) {
    int id = blockIdx.x * 256 + threadIdx.x;          // 4096 words * 64 float4
    if (id >= 4096 * 64) return;
    int word = id >> 6;
    int k4 = id & 63;
    int idx = sent[word];
    float4 v = ((const float4*)Wwe)[idx * 64 + k4];
    ((float4*)g_x)[word * 96 + 32 + k4] = v;
}

// ---------------- char BiLSTM (final hidden only), FFMA2 ----------------
// grid (128, 2dirs), 256 threads = 8 warps, each warp owns 4 words for all 16 steps.
// smem: sW (ulonglong2[128][64]) 128KB | sCE 25600B | xh2 (u64[8][4][128]) 32768B | sIdx 2048B
#define CHAR_SMEM (131072 + 25600 + 32768 + 2048)
__global__ __launch_bounds__(256) void k_char(const int* __restrict__ charArr,
                                              const float* __restrict__ Wce,
                                              const float* __restrict__ cb_f,
                                              const float* __restrict__ cb_b) {
    extern __shared__ float sm[];
    ulonglong2* sW = (ulonglong2*)sm;                               // [128][64]
    float* sCE = sm + 32768;                                        // 6400 floats
    unsigned long long* sXH = (unsigned long long*)(sm + 39168);    // [8][4][128] u64
    int* sIdx = (int*)(sm + 39168 + 8192);                          // [8][4][16]

    int dir = blockIdx.y;
    int tid = threadIdx.x, warp = tid >> 5, lane = tid & 31;

    const float4* gw = ((const float4*)g_cWP) + dir * (128 * 64);
    float4* sW4 = (float4*)sW;
    for (int i = tid; i < 128 * 64; i += 256) sW4[i] = gw[i];
    for (int i = tid; i < 6400; i += 256) sCE[i] = Wce[i];

    int wordBase = blockIdx.x * 32 + warp * 4;
    for (int i = lane; i < 64; i += 32) {
        int wd = i >> 4, c = i & 15;
        sIdx[warp * 64 + i] = charArr[(wordBase + wd) * CC + c];
    }
    unsigned long long* xh = sXH + warp * 512;         // [4][128]
    #pragma unroll
    for (int wd = 0; wd < 4; wd++) { xh[wd * 128 + 64 + lane] = 0ull; xh[wd * 128 + 96 + lane] = 0ull; }

    const float* cb = dir ? cb_b : cb_f;
    int lB = lane + 32;
    unsigned long long bA01 = pk2(cb[lane], cb[64 + lane]);
    unsigned long long bA23 = pk2(cb[128 + lane], cb[192 + lane]);
    unsigned long long bB01 = pk2(cb[lB], cb[64 + lB]);
    unsigned long long bB23 = pk2(cb[128 + lB], cb[192 + lB]);
    __syncthreads();

    float cAx[4] = {0, 0, 0, 0}, cBx[4] = {0, 0, 0, 0};

    for (int t = 0; t < 16; t++) {
        int cidx = dir ? (15 - t) : t;
        #pragma unroll
        for (int wd = 0; wd < 4; wd++) {
            int idx = sIdx[warp * 64 + wd * 16 + cidx];
            float e0 = sCE[idx * 64 + lane];
            float e1 = sCE[idx * 64 + 32 + lane];
            xh[wd * 128 + lane] = pk2(e0, e0);
            xh[wd * 128 + 32 + lane] = pk2(e1, e1);
        }
        __syncwarp();
        unsigned long long aA01[4], aA23[4], aB01[4], aB23[4];
        #pragma unroll
        for (int wd = 0; wd < 4; wd++) {
            aA01[wd] = bA01; aA23[wd] = bA23; aB01[wd] = bB01; aB23[wd] = bB23;
        }
        #pragma unroll 2
        for (int k = 0; k < 128; k++) {
            ulonglong2 wA = sW[k * 64 + lane];
            ulonglong2 wB = sW[k * 64 + lane + 32];
            #pragma unroll
            for (int wd = 0; wd < 4; wd++) {
                unsigned long long xv = xh[wd * 128 + k];
                aA01[wd] = fma2(wA.x, xv, aA01[wd]);
                aA23[wd] = fma2(wA.y, xv, aA23[wd]);
                aB01[wd] = fma2(wB.x, xv, aB01[wd]);
                aB23[wd] = fma2(wB.y, xv, aB23[wd]);
            }
        }
        __syncwarp();   // everyone done reading old h before overwrite
        #pragma unroll
        for (int wd = 0; wd < 4; wd++) {
            float iA, fA, gA, oA, iB, fB, gB, oB;
            upk2(aA01[wd], iA, fA); upk2(aA23[wd], gA, oA);
            upk2(aB01[wd], iB, fB); upk2(aB23[wd], gB, oB);
            cAx[wd] = sigf(fA) * cAx[wd] + sigf(iA) * tanhf(gA);
            float hA = sigf(oA) * tanhf(cAx[wd]);
            cBx[wd] = sigf(fB) * cBx[wd] + sigf(iB) * tanhf(gB);
            float hB = sigf(oB) * tanhf(cBx[wd]);
            xh[wd * 128 + 64 + lane] = pk2(hA, hA);
            xh[wd * 128 + 96 + lane] = pk2(hB, hB);
        }
        __syncwarp();
    }
    // final h -> g_x[s][b][dir*64 + unit];  word n = b*S + s
    #pragma unroll
    for (int wd = 0; wd < 4; wd++) {
        int n = wordBase + wd;
        int b = n >> 7, s = n & 127;
        float* dst = g_x + (s * BB + b) * 384 + dir * 64;
        float hA, hB, dummy;
        upk2(xh[wd * 128 + 64 + lane], hA, dummy);
        upk2(xh[wd * 128 + 96 + lane], hB, dummy);
        dst[lane] = hA;
        dst[32 + lane] = hB;
    }
}

// ---------------- x-part GEMM (FFMA2, batch-pair packed): pre = x @ Wih^T + b ----------------
// grid (S, 2dirs, 2 batch-halves), 256 threads: thread = unit; 8 batch-pairs x 4 gates
__global__ __launch_bounds__(256) void k_pre(const float* __restrict__ wb_f,
                                             const float* __restrict__ wb_b) {
    __shared__ unsigned long long sxp[8][384];   // {x[b], x[b+8]} per k
    int s = blockIdx.x, dir = blockIdx.y, bh = blockIdx.z;
    int u = threadIdx.x;
    const float* xsrc = g_x + (s * BB + bh * 16) * 384;
    for (int i = u; i < 8 * 384; i += 256) {
        int b2 = i / 384, k = i % 384;
        sxp[b2][k] = pk2(xsrc[b2 * 384 + k], xsrc[(b2 + 8) * 384 + k]);
    }
    __syncthreads();

    unsigned long long a0[8], a1[8], a2[8], a3[8];
    #pragma unroll
    for (int p = 0; p < 8; p++) { a0[p] = 0ull; a1[p] = 0ull; a2[p] = 0ull; a3[p] = 0ull; }

    const float4* W = ((const float4*)g_WIP) + dir * (384 * 256);
    #pragma unroll 2
    for (int k = 0; k < 384; k++) {
        float4 w = W[k * 256 + u];
        unsigned long long w0 = pk2(w.x, w.x), w1 = pk2(w.y, w.y);
        unsigned long long w2 = pk2(w.z, w.z), w3 = pk2(w.w, w.w);
        #pragma unroll
        for (int p = 0; p < 8; p++) {
            unsigned long long xv = sxp[p][k];
            a0[p] = fma2(w0, xv, a0[p]);
            a1[p] = fma2(w1, xv, a1[p]);
            a2[p] = fma2(w2, xv, a2[p]);
            a3[p] = fma2(w3, xv, a3[p]);
        }
    }
    const float* wb = dir ? wb_b : wb_f;
    float bi = wb[u], bf = wb[256 + u], bg = wb[512 + u], bo = wb[768 + u];
    float4* dst = ((float4*)g_pre) + (((dir * SS + s) * BB) + bh * 16) * 256;
    #pragma unroll
    for (int p = 0; p < 8; p++) {
        float x0, y0, x1, y1, x2, y2, x3, y3;
        upk2(a0[p], x0, y0); upk2(a1[p], x1, y1);
        upk2(a2[p], x2, y2); upk2(a3[p], x3, y3);
        dst[p * 256 + u]       = make_float4(x0 + bi, x1 + bf, x2 + bg, x3 + bo);
        dst[(p + 8) * 256 + u] = make_float4(y0 + bi, y1 + bf, y2 + bg, y3 + bo);
    }
}

// ---------------- word LSTM recurrence: 8-CTA cluster, SMEM-resident Whh ----------------
// 16 clusters (dir x 8 batch-groups) x 8 CTAs; CTA rank owns units [rank*32, rank*32+32).
// 128 threads: thread = (u_loc = tid>>2, bl = tid&3). h exchanged via DSMEM, double-buffered.
#define REC_SMEM (131072 + 16384)   // sW [256][32] ulonglong2 (128KB) + h2 [2][4][256] u64 (16KB)
__global__ __launch_bounds__(128, 1) __cluster_dims__(8, 1, 1) void k_rec2() {
    extern __shared__ float smr[];
    ulonglong2* sW = (ulonglong2*)smr;                               // [k=256][u_loc=32]
    unsigned long long* h2 = (unsigned long long*)(smr + 32768);     // [2][4][256] {h,h}

    int cta = blockIdx.x;
    int rank = cta & 7, cid = cta >> 3;
    int dir = cid & 1, bg = cid >> 1;
    int tid = threadIdx.x;
    int u = tid >> 2, bl = tid & 3;
    int uG = rank * 32 + u;
    int bG = bg * 4 + bl;

    // load Whh slice: [k][uG] float4 == ulonglong2 {(i,f),(g,o)}
    const float4* g4 = ((const float4*)g_WHP) + dir * 65536;
    float4* sW4 = (float4*)sW;
    for (int i = tid; i < 8192; i += 128) {
        int k = i >> 5, uu = i & 31;
        sW4[i] = g4[k * 256 + rank * 32 + uu];
    }
    // zero own h buffer 0
    for (int i = tid; i < 1024; i += 128) h2[i] = 0ull;
    __syncthreads();
    CLUSTER_SYNC_();

    unsigned int h2_sa = smem_u32(h2);
    const ulonglong2* pre2 = (const ulonglong2*)g_pre;
    float c = 0.f;
    int cur = 0;

    for (int t = 0; t < SS; t++) {
        int s = dir ? (SS - 1 - t) : t;
        ulonglong2 av = pre2[(size_t)((dir * SS + s) * BB + bG) * 256 + uG];
        unsigned long long a01 = av.x, a23 = av.y;      // even chain (seeded with pre)
        unsigned long long b01 = 0ull, b23 = 0ull;      // odd chain
        const unsigned long long* hb = h2 + cur * 1024 + bl * 256;
        #pragma unroll 8
        for (int k = 0; k < 256; k += 2) {
            ulonglong2 w0 = sW[k * 32 + u];
            ulonglong2 w1 = sW[(k + 1) * 32 + u];
            unsigned long long h0 = hb[k];
            unsigned long long h1 = hb[k + 1];
            a01 = fma2(w0.x, h0, a01);
            a23 = fma2(w0.y, h0, a23);
            b01 = fma2(w1.x, h1, b01);
            b23 = fma2(w1.y, h1, b23);
        }
        a01 = add2(a01, b01);
        a23 = add2(a23, b23);
        float gi, gf, gg, go;
        upk2(a01, gi, gf); upk2(a23, gg, go);
        c = sigf(gf) * c + sigf(gi) * tanhf(gg);
        float h = sigf(go) * tanhf(c);

        int nxt = cur ^ 1;
        unsigned long long hp = pk2(h, h);
        unsigned int off = h2_sa + (unsigned)((nxt * 1024 + bl * 256 + uG) * 8);
        #pragma unroll
        for (int r = 0; r < 8; r++) {
            unsigned int ra;
            asm volatile("mapa.shared::cluster.u32 %0, %1, %2;" : "=r"(ra) : "r"(off), "r"(r));
            asm volatile("st.shared::cluster.b64 [%0], %1;" :: "r"(ra), "l"(hp) : "memory");
        }
        g_out[(s * BB + bG) * 512 + dir * 256 + uG] = h;
        CLUSTER_SYNC_();            // release/acquire: h(t+1) visible cluster-wide
        cur = nxt;
    }
}

// ---------------- emissions: em = out @ emit_W^T + emit_b ----------------
__global__ __launch_bounds__(544) void k_em(const float* __restrict__ emW,
                                            const float* __restrict__ emb) {
    extern __shared__ float sm[];
    float* sO = sm;                // [32][513]
    float* sE = sm + 32 * 513;     // [17][513]
    int s = blockIdx.x, tid = threadIdx.x;
    const float* osrc = g_out + s * BB * 512;
    for (int i = tid; i < 32 * 512; i += 544) sO[(i >> 9) * 513 + (i & 511)] = osrc[i];
    for (int i = tid; i < 17 * 512; i += 544) sE[(i / 512) * 513 + (i % 512)] = emW[i];
    __syncthreads();
    int b = tid / 17, j = tid % 17;
    const float* ro = sO + b * 513;
    const float* rw = sE + j * 513;
    float acc = emb[j];
    #pragma unroll 8
    for (int k = 0; k < 512; k++) acc = fmaf(ro[k], rw[k], acc);
    g_em[(s * BB + b) * NT + j] = acc;
}

// ---------------- CRF: per-batch num & den ----------------
__global__ void k_crf(const int* __restrict__ tags, const float* __restrict__ trans,
                      const float* __restrict__ startv, const float* __restrict__ endv) {
    __shared__ float sE[NT][18], sT[NT][18], sU[32];
    int b = blockIdx.x, lane = threadIdx.x;
    for (int i = lane; i < NT * NT; i += 32) {
        float v = trans[i];
        sT[i / NT][i % NT] = v;
        sE[i / NT][i % NT] = expf(v);
    }
    __syncwarp();
    float alpha = -1e30f;
    if (lane < NT) alpha = startv[lane] + g_em[b * NT + lane];
    for (int t = 1; t < SS; t++) {
        float m = alpha;
        #pragma unroll
        for (int o = 16; o > 0; o >>= 1) m = fmaxf(m, __shfl_xor_sync(0xffffffffu, m, o));
        float uu = expf(alpha - m);            // lanes >= 17 -> 0
        sU[lane] = uu;
        __syncwarp();
        if (lane < NT) {
            float ssum = 0.f;
            #pragma unroll
            for (int i = 0; i < NT; i++) ssum = fmaf(sU[i], sE[i][lane], ssum);
            alpha = m + logf(ssum) + g_em[(t * BB + b) * NT + lane];
        }
        __syncwarp();
    }
    float v = (lane < NT) ? (alpha + endv[lane]) : -1e30f;
    float m2 = v;
    #pragma unroll
    for (int o = 16; o > 0; o >>= 1) m2 = fmaxf(m2, __shfl_xor_sync(0xffffffffu, m2, o));
    float e2 = expf(v - m2);
    #pragma unroll
    for (int o = 16; o > 0; o >>= 1) e2 += __shfl_xor_sync(0xffffffffu, e2, o);
    float den = m2 + logf(e2);

    // numerator (mask always true: sentence ids >= 2)
    float part = 0.f;
    for (int t = lane; t < SS; t += 32) {
        int tg = tags[t * BB + b];
        part += g_em[(t * BB + b) * NT + tg];
        if (t > 0) {
            int tp = tags[(t - 1) * BB + b];
            part += sT[tp][tg];
        }
    }
    #pragma unroll
    for (int o = 16; o > 0; o >>= 1) part += __shfl_xor_sync(0xffffffffu, part, o);
    if (lane == 0) {
        int t0 = tags[b];
        int tl = tags[(SS - 1) * BB + b];
        float num = part + startv[t0] + endv[tl];
        g_part[b] = num - den;
    }
}

__global__ void k_final(float* out) {
    int lane = threadIdx.x;
    float v = g_part[lane];
    #pragma unroll
    for (int o = 16; o > 0; o >>= 1) v += __shfl_xor_sync(0xffffffffu, v, o);
    if (lane == 0) out[0] = -v;
}

// ---------------- launch ----------------
extern "C" void kernel_launch(void* const* d_in, const int* in_sizes, int n_in,
                              void* d_out, int out_size) {
    const int* sent = (const int*)d_in[0];
    const int* ch   = (const int*)d_in[1];
    const int* tags = (const int*)d_in[2];
    const float* Wwe = (const float*)d_in[3];
    const float* Wce = (const float*)d_in[4];
    const float* c_Wih_f = (const float*)d_in[5];
    const float* c_Whh_f = (const float*)d_in[6];
    const float* c_b_f   = (const float*)d_in[7];
    const float* c_Wih_b = (const float*)d_in[8];
    const float* c_Whh_b = (const float*)d_in[9];
    const float* c_b_b   = (const float*)d_in[10];
    const float* w_Wih_f = (const float*)d_in[11];
    const float* w_Whh_f = (const float*)d_in[12];
    const float* w_b_f   = (const float*)d_in[13];
    const float* w_Wih_b = (const float*)d_in[14];
    const float* w_Whh_b = (const float*)d_in[15];
    const float* w_b_b   = (const float*)d_in[16];
    const float* emW  = (const float*)d_in[17];
    const float* emb  = (const float*)d_in[18];
    const float* trans  = (const float*)d_in[19];
    const float* startv = (const float*)d_in[20];
    const float* endv   = (const float*)d_in[21];

    const int EM_SMEM = (32 * 513 + 17 * 513) * 4;
    cudaFuncSetAttribute(k_char, cudaFuncAttributeMaxDynamicSharedMemorySize, CHAR_SMEM);
    cudaFuncSetAttribute(k_rec2, cudaFuncAttributeMaxDynamicSharedMemorySize, REC_SMEM);
    cudaFuncSetAttribute(k_em, cudaFuncAttributeMaxDynamicSharedMemorySize, EM_SMEM);

    k_prep_char<<<256, 256>>>(c_Wih_f, c_Whh_f, c_Wih_b, c_Whh_b);
    k_prep_word<<<5120, 256>>>(w_Wih_f, w_Whh_f, w_Wih_b, w_Whh_b);
    k_gather<<<1024, 256>>>(sent, Wwe);
    k_char<<<dim3(128, 2), 256, CHAR_SMEM>>>(ch, Wce, c_b_f, c_b_b);
    k_pre<<<dim3(128, 2, 2), 256>>>(w_b_f, w_b_b);
    k_rec2<<<128, 128, REC_SMEM>>>();
    k_em<<<128, 544, EM_SMEM>>>(emW, emb);
    k_crf<<<32, 32>>>(tags, trans, startv, endv);
    k_final<<<1, 32>>>((float*)d_out);
}

// round 13
// speedup vs baseline: 2.6415x; 1.1345x over previous
#include <cuda_runtime.h>
#include <cuda_bf16.h>
#include <math.h>

#define SS 128
#define BB 32
#define CC 16
#define NT 17

// ---------------- scratch ----------------
__device__ float g_cWP[2][128][64][4];          // char weights permuted [dir][k][unit][ifgo]
__device__ float g_P[2][100][64][4];            // per-char table: Wih@emb + b
__device__ float g_WIP[2][384][256][4];         // word Wih permuted
__device__ float g_WHP[2][256][256][4];         // word Whh permuted
__device__ float g_x[SS * BB * 384];
__device__ float g_pre[2][SS][BB][1024];
__device__ float g_out[SS * BB * 512];
__device__ float g_em[SS * BB * NT];
__device__ float g_part[BB];

__device__ __forceinline__ float sigf(float x) { return 1.0f / (1.0f + expf(-x)); }

__device__ __forceinline__ unsigned long long pk2(float a, float b) {
    unsigned long long r;
    asm("mov.b64 %0, {%1, %2};" : "=l"(r) : "r"(__float_as_uint(a)), "r"(__float_as_uint(b)));
    return r;
}
__device__ __forceinline__ void upk2(unsigned long long v, float& a, float& b) {
    unsigned int x, y;
    asm("mov.b64 {%0, %1}, %2;" : "=r"(x), "=r"(y) : "l"(v));
    a = __uint_as_float(x); b = __uint_as_float(y);
}
__device__ __forceinline__ unsigned long long fma2(unsigned long long a, unsigned long long b,
                                                   unsigned long long c) {
    unsigned long long d;
    asm("fma.rn.f32x2 %0, %1, %2, %3;" : "=l"(d) : "l"(a), "l"(b), "l"(c));
    return d;
}
__device__ __forceinline__ unsigned long long add2(unsigned long long a, unsigned long long b) {
    unsigned long long d;
    asm("add.rn.f32x2 %0, %1, %2;" : "=l"(d) : "l"(a), "l"(b));
    return d;
}
__device__ __forceinline__ unsigned int smem_u32(const void* p) {
    unsigned int a;
    asm("{ .reg .u64 t; cvta.to.shared.u64 t, %1; cvt.u32.u64 %0, t; }" : "=r"(a) : "l"(p));
    return a;
}
#define CLUSTER_SYNC_() do {                                          \
    asm volatile("barrier.cluster.arrive.aligned;" ::: "memory");     \
    asm volatile("barrier.cluster.wait.aligned;" ::: "memory");       \
} while (0)
#define MBAR_INIT_(a, c) \
    asm volatile("mbarrier.init.shared.b64 [%0], %1;" :: "r"(a), "r"(c) : "memory")
#define MBAR_EXPECT_(a, n) \
    asm volatile("mbarrier.arrive.expect_tx.shared.b64 _, [%0], %1;" :: "r"(a), "r"(n) : "memory")
#define ST_ASYNC64_(ra, v, rm) \
    asm volatile("st.async.shared::cluster.mbarrier::complete_tx::bytes.b64 [%0], %1, [%2];" \
                 :: "r"(ra), "l"(v), "r"(rm) : "memory")
__device__ __forceinline__ void mbar_wait(unsigned int a, unsigned int p) {
    asm volatile(
        "{\n\t.reg .pred P;\n\tWL%=:\n\t"
        "mbarrier.try_wait.parity.acquire.cluster.shared::cta.b64 P, [%0], %1;\n\t"
        "@!P bra WL%=;\n\t}"
        :: "r"(a), "r"(p) : "memory");
}

// ---------------- weight prep ----------------
__global__ void k_prep_char(const float* __restrict__ wih_f, const float* __restrict__ whh_f,
                            const float* __restrict__ wih_b, const float* __restrict__ whh_b) {
    int id = blockIdx.x * 256 + threadIdx.x;
    if (id >= 65536) return;
    int dir = id / 32768; int r = id % 32768;
    int k = r >> 8; int uq = r & 255; int u = uq >> 2; int q = uq & 3;
    const float* Wih = dir ? wih_b : wih_f;
    const float* Whh = dir ? whh_b : whh_f;
    int row = q * 64 + u;
    float v = (k < 64) ? Wih[row * 64 + k] : Whh[row * 64 + (k - 64)];
    g_cWP[dir][k][u][q] = v;
}

// per-char table: P[dir][c][u][g] = cb[g*64+u] + sum_k Wih[g*64+u][k]*emb[c][k]
__global__ void k_prep_P(const float* __restrict__ Wce,
                         const float* __restrict__ wih_f, const float* __restrict__ wih_b,
                         const float* __restrict__ cb_f, const float* __restrict__ cb_b) {
    __shared__ float sEmb[64];
    int dir = blockIdx.x / 100, c = blockIdx.x % 100;
    int tid = threadIdx.x;
    if (tid < 64) sEmb[tid] = Wce[c * 64 + tid];
    __syncthreads();
    int u = tid >> 2, g = tid & 3;
    const float* Wih = dir ? wih_b : wih_f;
    const float* cb = dir ? cb_b : cb_f;
    int row = g * 64 + u;
    float acc = cb[row];
    #pragma unroll 8
    for (int k = 0; k < 64; k++) acc = fmaf(Wih[row * 64 + k], sEmb[k], acc);
    g_P[dir][c][u][g] = acc;
}

__global__ void k_prep_word(const float* __restrict__ wih_f, const float* __restrict__ whh_f,
                            const float* __restrict__ wih_b, const float* __restrict__ whh_b) {
    int id = blockIdx.x * 256 + threadIdx.x;
    if (id < 786432) {
        int dir = id / 393216; int r = id % 393216;
        int k = r >> 10; int uq = r & 1023; int u = uq >> 2; int q = uq & 3;
        const float* W = dir ? wih_b : wih_f;
        g_WIP[dir][k][u][q] = W[(q * 256 + u) * 384 + k];
    } else if (id < 786432 + 524288) {
        int r2 = id - 786432;
        int dir = r2 / 262144; int r = r2 % 262144;
        int k = r >> 10; int uq = r & 1023; int u = uq >> 2; int q = uq & 3;
        const float* W = dir ? whh_b : whh_f;
        g_WHP[dir][k][u][q] = W[(q * 256 + u) * 256 + k];
    }
}

__global__ void k_gather(const int* __restrict__ sent, const float* __restrict__ Wwe) {
    int id = blockIdx.x * 256 + threadIdx.x;
    if (id >= 4096 * 64) return;
    int word = id >> 6;
    int k4 = id & 63;
    int idx = sent[word];
    float4 v = ((const float4*)Wwe)[idx * 64 + k4];
    ((float4*)g_x)[word * 96 + 32 + k4] = v;
}

// ---------------- char BiLSTM: P-seeded, h-only recurrence (k=64) ----------------
// grid (64, 2dirs), 256 threads = 8 warps x 8 words each.
// smem: sW (float4[64][64]) 64KB | sP (float4[100][64]) 100KB | xh u64[8][8][64] 32KB | sIdx 4KB
#define CHAR_SMEM (65536 + 102400 + 32768 + 4096)
__global__ __launch_bounds__(256) void k_char(const int* __restrict__ charArr) {
    extern __shared__ float sm[];
    ulonglong2* sW2 = (ulonglong2*)sm;                               // [64 k][64 u]
    float4* sW4 = (float4*)sm;
    ulonglong2* sP2 = (ulonglong2*)(sm + 16384);                     // [100 c][64 u]
    float4* sP4 = (float4*)(sm + 16384);
    unsigned long long* sXH = (unsigned long long*)(sm + 41984);     // [8 w][8 wd][64]
    int* sIdx = (int*)(sm + 50176);                                  // [64][16]

    int dir = blockIdx.y;
    int tid = threadIdx.x, warp = tid >> 5, lane = tid & 31;

    const float4* gw = ((const float4*)g_cWP) + dir * (128 * 64);
    for (int i = tid; i < 4096; i += 256) sW4[i] = gw[(64 + (i >> 6)) * 64 + (i & 63)];
    const float4* gp = ((const float4*)g_P) + dir * 6400;
    for (int i = tid; i < 6400; i += 256) sP4[i] = gp[i];
    for (int i = tid; i < 1024; i += 256)
        sIdx[i] = charArr[(blockIdx.x * 64 + (i >> 4)) * CC + (i & 15)];
    for (int i = tid; i < 4096; i += 256) sXH[i] = 0ull;
    __syncthreads();

    unsigned long long* xh = sXH + warp * 512;        // [8 wd][64]
    const int* widx = sIdx + warp * 128;              // [8 wd][16]
    int wordBase = blockIdx.x * 64 + warp * 8;
    float cA[8] = {0,0,0,0,0,0,0,0}, cB[8] = {0,0,0,0,0,0,0,0};

    for (int t = 0; t < 16; t++) {
        int cidx = dir ? (15 - t) : t;
        unsigned long long aA01[8], aA23[8], aB01[8], aB23[8];
        #pragma unroll
        for (int wd = 0; wd < 8; wd++) {
            int c = widx[wd * 16 + cidx];
            ulonglong2 pa = sP2[c * 64 + lane];
            ulonglong2 pb = sP2[c * 64 + 32 + lane];
            aA01[wd] = pa.x; aA23[wd] = pa.y;
            aB01[wd] = pb.x; aB23[wd] = pb.y;
        }
        #pragma unroll 2
        for (int k = 0; k < 64; k++) {
            ulonglong2 wA = sW2[k * 64 + lane];
            ulonglong2 wB = sW2[k * 64 + 32 + lane];
            #pragma unroll
            for (int wd = 0; wd < 8; wd++) {
                unsigned long long xv = xh[wd * 64 + k];
                aA01[wd] = fma2(wA.x, xv, aA01[wd]);
                aA23[wd] = fma2(wA.y, xv, aA23[wd]);
                aB01[wd] = fma2(wB.x, xv, aB01[wd]);
                aB23[wd] = fma2(wB.y, xv, aB23[wd]);
            }
        }
        __syncwarp();   // reads of old h done
        #pragma unroll
        for (int wd = 0; wd < 8; wd++) {
            float i0, f0, gg0, o0;
            upk2(aA01[wd], i0, f0); upk2(aA23[wd], gg0, o0);
            cA[wd] = sigf(f0) * cA[wd] + sigf(i0) * tanhf(gg0);
            float hA = sigf(o0) * tanhf(cA[wd]);
            upk2(aB01[wd], i0, f0); upk2(aB23[wd], gg0, o0);
            cB[wd] = sigf(f0) * cB[wd] + sigf(i0) * tanhf(gg0);
            float hB = sigf(o0) * tanhf(cB[wd]);
            xh[wd * 64 + lane] = pk2(hA, hA);
            xh[wd * 64 + 32 + lane] = pk2(hB, hB);
        }
        __syncwarp();
    }
    #pragma unroll
    for (int wd = 0; wd < 8; wd++) {
        int n = wordBase + wd;
        int b = n >> 7, s = n & 127;
        float* dst = g_x + (s * BB + b) * 384 + dir * 64;
        float hA, hB, d0;
        upk2(xh[wd * 64 + lane], hA, d0);
        upk2(xh[wd * 64 + 32 + lane], hB, d0);
        dst[lane] = hA;
        dst[32 + lane] = hB;
    }
}

// ---------------- x-part GEMM with weight prefetch ----------------
__global__ __launch_bounds__(256) void k_pre(const float* __restrict__ wb_f,
                                             const float* __restrict__ wb_b) {
    __shared__ unsigned long long sxp[8][384];
    int s = blockIdx.x, dir = blockIdx.y, bh = blockIdx.z;
    int u = threadIdx.x;
    const float* xsrc = g_x + (s * BB + bh * 16) * 384;
    for (int i = u; i < 8 * 384; i += 256) {
        int b2 = i / 384, k = i % 384;
        sxp[b2][k] = pk2(xsrc[b2 * 384 + k], xsrc[(b2 + 8) * 384 + k]);
    }
    __syncthreads();

    unsigned long long a0[8], a1[8], a2[8], a3[8];
    #pragma unroll
    for (int p = 0; p < 8; p++) { a0[p] = 0ull; a1[p] = 0ull; a2[p] = 0ull; a3[p] = 0ull; }

    const float4* Wp = ((const float4*)g_WIP) + dir * (384 * 256) + u;
    float4 w = Wp[0];
    #pragma unroll 2
    for (int k = 0; k < 384; k++) {
        float4 wn = (k < 383) ? Wp[(k + 1) * 256] : w;    // prefetch next row
        unsigned long long w0 = pk2(w.x, w.x), w1 = pk2(w.y, w.y);
        unsigned long long w2 = pk2(w.z, w.z), w3 = pk2(w.w, w.w);
        #pragma unroll
        for (int p = 0; p < 8; p++) {
            unsigned long long xv = sxp[p][k];
            a0[p] = fma2(w0, xv, a0[p]);
            a1[p] = fma2(w1, xv, a1[p]);
            a2[p] = fma2(w2, xv, a2[p]);
            a3[p] = fma2(w3, xv, a3[p]);
        }
        w = wn;
    }
    const float* wb = dir ? wb_b : wb_f;
    float bi = wb[u], bf = wb[256 + u], bg = wb[512 + u], bo = wb[768 + u];
    float4* dst = ((float4*)g_pre) + (((dir * SS + s) * BB) + bh * 16) * 256;
    #pragma unroll
    for (int p = 0; p < 8; p++) {
        float x0, y0, x1, y1, x2, y2, x3, y3;
        upk2(a0[p], x0, y0); upk2(a1[p], x1, y1);
        upk2(a2[p], x2, y2); upk2(a3[p], x3, y3);
        dst[p * 256 + u]       = make_float4(x0 + bi, x1 + bf, x2 + bg, x3 + bo);
        dst[(p + 8) * 256 + u] = make_float4(y0 + bi, y1 + bf, y2 + bg, y3 + bo);
    }
}

// ---------------- word LSTM: 8-CTA cluster, SMEM Whh, st.async + tx-mbarrier sync --------
// smem bytes: sW [256][32] ulonglong2 @0 (128KB) | h2 [2][4][256] u64 @131072 (16KB)
//             | 2 mbarriers @147456
#define H2_OFF 131072
#define MBAR_OFF 147456
#define REC_SMEM (147456 + 64)
__global__ __launch_bounds__(128, 1) __cluster_dims__(8, 1, 1) void k_rec2() {
    extern __shared__ float smr[];
    ulonglong2* sW = (ulonglong2*)smr;                               // [k=256][u_loc=32]
    unsigned long long* h2 = (unsigned long long*)(smr + 32768);     // [2][4][256] {h,h}

    int cta = blockIdx.x;
    int rank = cta & 7, cid = cta >> 3;
    int dir = cid & 1, bg = cid >> 1;
    int tid = threadIdx.x;
    int u = tid >> 2, bl = tid & 3;
    int uG = rank * 32 + u;
    int bG = bg * 4 + bl;

    unsigned int sbase = smem_u32(smr);
    const float4* g4 = ((const float4*)g_WHP) + dir * 65536;
    float4* sW4 = (float4*)sW;
    for (int i = tid; i < 8192; i += 128) {
        int k = i >> 5, uu = i & 31;
        sW4[i] = g4[k * 256 + rank * 32 + uu];
    }
    for (int i = tid; i < 1024; i += 128) h2[i] = 0ull;   // zero buffer 0
    if (tid == 0) {
        MBAR_INIT_(sbase + MBAR_OFF, 1);
        MBAR_INIT_(sbase + MBAR_OFF + 8, 1);
    }
    __syncthreads();
    CLUSTER_SYNC_();   // remote mbarriers + buffers initialized before any st.async

    // precompute remote smem bases per rank (mapa is offset-additive within a CTA)
    unsigned int rb[8];
    #pragma unroll
    for (int r = 0; r < 8; r++)
        asm("mapa.shared::cluster.u32 %0, %1, %2;" : "=r"(rb[r]) : "r"(sbase), "r"(r));

    const ulonglong2* pre2 = (const ulonglong2*)g_pre;
    float c = 0.f;
    int cur = 0;
    unsigned int ph0 = 0, ph1 = 0;
    int s0 = dir ? (SS - 1) : 0;
    ulonglong2 av = pre2[(size_t)((dir * SS + s0) * BB + bG) * 256 + uG];

    for (int t = 0; t < SS; t++) {
        int s = dir ? (SS - 1 - t) : t;
        unsigned long long a01 = av.x, a23 = av.y;
        if (t + 1 < SS) {   // prefetch next pre row (hides L2 latency behind the k-loop)
            int sn = dir ? (SS - 2 - t) : (t + 1);
            av = pre2[(size_t)((dir * SS + sn) * BB + bG) * 256 + uG];
        }
        unsigned long long b01 = 0ull, b23 = 0ull;
        const unsigned long long* hb = h2 + cur * 1024 + bl * 256;
        #pragma unroll 8
        for (int k = 0; k < 256; k += 2) {
            ulonglong2 w0 = sW[k * 32 + u];
            ulonglong2 w1 = sW[(k + 1) * 32 + u];
            unsigned long long hh0 = hb[k];
            unsigned long long hh1 = hb[k + 1];
            a01 = fma2(w0.x, hh0, a01);
            a23 = fma2(w0.y, hh0, a23);
            b01 = fma2(w1.x, hh1, b01);
            b23 = fma2(w1.y, hh1, b23);
        }
        a01 = add2(a01, b01);
        a23 = add2(a23, b23);
        float gi, gf, gg, go;
        upk2(a01, gi, gf); upk2(a23, gg, go);
        c = sigf(gf) * c + sigf(gi) * tanhf(gg);
        float h = sigf(go) * tanhf(c);
        g_out[(s * BB + bG) * 512 + dir * 256 + uG] = h;

        if (t + 1 < SS) {
            int nxt = cur ^ 1;
            if (tid == 0) MBAR_EXPECT_(sbase + MBAR_OFF + nxt * 8, 8192);
            unsigned long long hp = pk2(h, h);
            unsigned int hoff = (unsigned)(H2_OFF + (nxt * 1024 + bl * 256 + uG) * 8);
            unsigned int moff = (unsigned)(MBAR_OFF + nxt * 8);
            #pragma unroll
            for (int r = 0; r < 8; r++)
                ST_ASYNC64_(rb[r] + hoff, hp, rb[r] + moff);
            // tx-complete of nxt certifies every CTA finished reading cur -> safe reuse
            if (nxt == 0) { mbar_wait(sbase + MBAR_OFF, ph0); ph0 ^= 1; }
            else          { mbar_wait(sbase + MBAR_OFF + 8, ph1); ph1 ^= 1; }
            cur = nxt;
        }
    }
}

// ---------------- emissions ----------------
__global__ __launch_bounds__(544) void k_em(const float* __restrict__ emW,
                                            const float* __restrict__ emb) {
    extern __shared__ float sm[];
    float* sO = sm;                // [32][513]
    float* sE = sm + 32 * 513;     // [17][513]
    int s = blockIdx.x, tid = threadIdx.x;
    const float* osrc = g_out + s * BB * 512;
    for (int i = tid; i < 32 * 512; i += 544) sO[(i >> 9) * 513 + (i & 511)] = osrc[i];
    for (int i = tid; i < 17 * 512; i += 544) sE[(i / 512) * 513 + (i % 512)] = emW[i];
    __syncthreads();
    int b = tid / 17, j = tid % 17;
    const float* ro = sO + b * 513;
    const float* rw = sE + j * 513;
    float acc = emb[j];
    #pragma unroll 8
    for (int k = 0; k < 512; k++) acc = fmaf(ro[k], rw[k], acc);
    g_em[(s * BB + b) * NT + j] = acc;
}

// ---------------- CRF ----------------
__global__ void k_crf(const int* __restrict__ tags, const float* __restrict__ trans,
                      const float* __restrict__ startv, const float* __restrict__ endv) {
    __shared__ float sE[NT][18], sT[NT][18], sU[32];
    int b = blockIdx.x, lane = threadIdx.x;
    for (int i = lane; i < NT * NT; i += 32) {
        float v = trans[i];
        sT[i / NT][i % NT] = v;
        sE[i / NT][i % NT] = expf(v);
    }
    __syncwarp();
    float alpha = -1e30f;
    if (lane < NT) alpha = startv[lane] + g_em[b * NT + lane];
    float emv = (lane < NT) ? g_em[(BB + b) * NT + lane] : 0.f;   // em row t=1
    for (int t = 1; t < SS; t++) {
        float emn = (t + 1 < SS && lane < NT) ? g_em[((t + 1) * BB + b) * NT + lane] : 0.f;
        float m = alpha;
        #pragma unroll
        for (int o = 16; o > 0; o >>= 1) m = fmaxf(m, __shfl_xor_sync(0xffffffffu, m, o));
        sU[lane] = expf(alpha - m);            // lanes >= 17 -> 0
        __syncwarp();
        if (lane < NT) {
            float ssum = 0.f;
            #pragma unroll
            for (int i = 0; i < NT; i++) ssum = fmaf(sU[i], sE[i][lane], ssum);
            alpha = m + logf(ssum) + emv;
        }
        __syncwarp();
        emv = emn;
    }
    float v = (lane < NT) ? (alpha + endv[lane]) : -1e30f;
    float m2 = v;
    #pragma unroll
    for (int o = 16; o > 0; o >>= 1) m2 = fmaxf(m2, __shfl_xor_sync(0xffffffffu, m2, o));
    float e2 = expf(v - m2);
    #pragma unroll
    for (int o = 16; o > 0; o >>= 1) e2 += __shfl_xor_sync(0xffffffffu, e2, o);
    float den = m2 + logf(e2);

    float part = 0.f;
    for (int t = lane; t < SS; t += 32) {
        int tg = tags[t * BB + b];
        part += g_em[(t * BB + b) * NT + tg];
        if (t > 0) part += sT[tags[(t - 1) * BB + b]][tg];
    }
    #pragma unroll
    for (int o = 16; o > 0; o >>= 1) part += __shfl_xor_sync(0xffffffffu, part, o);
    if (lane == 0) {
        float num = part + startv[tags[b]] + endv[tags[(SS - 1) * BB + b]];
        g_part[b] = num - den;
    }
}

__global__ void k_final(float* out) {
    int lane = threadIdx.x;
    float v = g_part[lane];
    #pragma unroll
    for (int o = 16; o > 0; o >>= 1) v += __shfl_xor_sync(0xffffffffu, v, o);
    if (lane == 0) out[0] = -v;
}

// ---------------- launch ----------------
extern "C" void kernel_launch(void* const* d_in, const int* in_sizes, int n_in,
                              void* d_out, int out_size) {
    const int* sent = (const int*)d_in[0];
    const int* ch   = (const int*)d_in[1];
    const int* tags = (const int*)d_in[2];
    const float* Wwe = (const float*)d_in[3];
    const float* Wce = (const float*)d_in[4];
    const float* c_Wih_f = (const float*)d_in[5];
    const float* c_Whh_f = (const float*)d_in[6];
    const float* c_b_f   = (const float*)d_in[7];
    const float* c_Wih_b = (const float*)d_in[8];
    const float* c_Whh_b = (const float*)d_in[9];
    const float* c_b_b   = (const float*)d_in[10];
    const float* w_Wih_f = (const float*)d_in[11];
    const float* w_Whh_f = (const float*)d_in[12];
    const float* w_b_f   = (const float*)d_in[13];
    const float* w_Wih_b = (const float*)d_in[14];
    const float* w_Whh_b = (const float*)d_in[15];
    const float* w_b_b   = (const float*)d_in[16];
    const float* emW  = (const float*)d_in[17];
    const float* emb  = (const float*)d_in[18];
    const float* trans  = (const float*)d_in[19];
    const float* startv = (const float*)d_in[20];
    const float* endv   = (const float*)d_in[21];

    const int EM_SMEM = (32 * 513 + 17 * 513) * 4;
    cudaFuncSetAttribute(k_char, cudaFuncAttributeMaxDynamicSharedMemorySize, CHAR_SMEM);
    cudaFuncSetAttribute(k_rec2, cudaFuncAttributeMaxDynamicSharedMemorySize, REC_SMEM);
    cudaFuncSetAttribute(k_em, cudaFuncAttributeMaxDynamicSharedMemorySize, EM_SMEM);

    k_prep_char<<<256, 256>>>(c_Wih_f, c_Whh_f, c_Wih_b, c_Whh_b);
    k_prep_P<<<200, 256>>>(Wce, c_Wih_f, c_Wih_b, c_b_f, c_b_b);
    k_prep_word<<<5120, 256>>>(w_Wih_f, w_Whh_f, w_Wih_b, w_Whh_b);
    k_gather<<<1024, 256>>>(sent, Wwe);
    k_char<<<dim3(64, 2), 256, CHAR_SMEM>>>(ch);
    k_pre<<<dim3(128, 2, 2), 256>>>(w_b_f, w_b_b);
    k_rec2<<<128, 128, REC_SMEM>>>();
    k_em<<<128, 544, EM_SMEM>>>(emW, emb);
    k_crf<<<32, 32>>>(tags, trans, startv, endv);
    k_final<<<1, 32>>>((float*)d_out);
}

// round 14
// speedup vs baseline: 2.7841x; 1.0540x over previous
#include <cuda_runtime.h>
#include <cuda_bf16.h>
#include <math.h>

#define SS 128
#define BB 32
#define CC 16
#define NT 17

// ---------------- scratch ----------------
__device__ float g_cWP[2][128][64][4];          // char weights permuted [dir][k][unit][ifgo]
__device__ float g_P[2][100][64][4];            // per-char table: Wih@emb + b
__device__ float g_WIP2[2][2][384][512];        // word Wih gate-split [dir][gh][k][u*2+p]
__device__ float g_WHP[2][256][256][4];         // word Whh permuted
__device__ float g_x[SS * BB * 384];
__device__ float g_pre[2][SS][BB][1024];
__device__ float g_out[SS * BB * 512];
__device__ float g_em[SS * BB * NT];
__device__ float g_part[BB];

__device__ __forceinline__ float tanh_a(float x) {
    float y;
    asm("tanh.approx.f32 %0, %1;" : "=f"(y) : "f"(x));
    return y;
}
__device__ __forceinline__ float sig_a(float x) {
    return 0.5f * tanh_a(0.5f * x) + 0.5f;
}

__device__ __forceinline__ unsigned long long pk2(float a, float b) {
    unsigned long long r;
    asm("mov.b64 %0, {%1, %2};" : "=l"(r) : "r"(__float_as_uint(a)), "r"(__float_as_uint(b)));
    return r;
}
__device__ __forceinline__ void upk2(unsigned long long v, float& a, float& b) {
    unsigned int x, y;
    asm("mov.b64 {%0, %1}, %2;" : "=r"(x), "=r"(y) : "l"(v));
    a = __uint_as_float(x); b = __uint_as_float(y);
}
__device__ __forceinline__ unsigned long long fma2(unsigned long long a, unsigned long long b,
                                                   unsigned long long c) {
    unsigned long long d;
    asm("fma.rn.f32x2 %0, %1, %2, %3;" : "=l"(d) : "l"(a), "l"(b), "l"(c));
    return d;
}
__device__ __forceinline__ unsigned long long add2(unsigned long long a, unsigned long long b) {
    unsigned long long d;
    asm("add.rn.f32x2 %0, %1, %2;" : "=l"(d) : "l"(a), "l"(b));
    return d;
}
__device__ __forceinline__ unsigned int smem_u32(const void* p) {
    unsigned int a;
    asm("{ .reg .u64 t; cvta.to.shared.u64 t, %1; cvt.u32.u64 %0, t; }" : "=r"(a) : "l"(p));
    return a;
}
#define CLUSTER_SYNC_() do {                                          \
    asm volatile("barrier.cluster.arrive.aligned;" ::: "memory");     \
    asm volatile("barrier.cluster.wait.aligned;" ::: "memory");       \
} while (0)
#define MBAR_INIT_(a, c) \
    asm volatile("mbarrier.init.shared.b64 [%0], %1;" :: "r"(a), "r"(c) : "memory")
#define MBAR_EXPECT_(a, n) \
    asm volatile("mbarrier.arrive.expect_tx.shared.b64 _, [%0], %1;" :: "r"(a), "r"(n) : "memory")
#define ST_ASYNC64_(ra, v, rm) \
    asm volatile("st.async.shared::cluster.mbarrier::complete_tx::bytes.b64 [%0], %1, [%2];" \
                 :: "r"(ra), "l"(v), "r"(rm) : "memory")
__device__ __forceinline__ void mbar_wait(unsigned int a, unsigned int p) {
    asm volatile(
        "{\n\t.reg .pred P;\n\tWL%=:\n\t"
        "mbarrier.try_wait.parity.acquire.cluster.shared::cta.b64 P, [%0], %1;\n\t"
        "@!P bra WL%=;\n\t}"
        :: "r"(a), "r"(p) : "memory");
}

// ---------------- fused prep: all permutes + P table + word-emb gather ----------------
// blocks: A [0,256) char perm | B [256,456) P | C [456,2504) Whh perm
//         D [2504,5576) Wih gate-split | E [5576,6600) gather
__global__ void k_prep_all(const float* __restrict__ c_wih_f, const float* __restrict__ c_whh_f,
                           const float* __restrict__ c_wih_b, const float* __restrict__ c_whh_b,
                           const float* __restrict__ cb_f, const float* __restrict__ cb_b,
                           const float* __restrict__ w_wih_f, const float* __restrict__ w_whh_f,
                           const float* __restrict__ w_wih_b, const float* __restrict__ w_whh_b,
                           const float* __restrict__ Wce,
                           const int* __restrict__ sent, const float* __restrict__ Wwe) {
    __shared__ float sEmb[64];
    int blk = blockIdx.x, tid = threadIdx.x;
    if (blk < 256) {
        int id = blk * 256 + tid;
        int dir = id / 32768; int r = id % 32768;
        int k = r >> 8; int uq = r & 255; int u = uq >> 2; int q = uq & 3;
        const float* Wih = dir ? c_wih_b : c_wih_f;
        const float* Whh = dir ? c_whh_b : c_whh_f;
        int row = q * 64 + u;
        float v = (k < 64) ? Wih[row * 64 + k] : Whh[row * 64 + (k - 64)];
        g_cWP[dir][k][u][q] = v;
    } else if (blk < 456) {
        int bc = blk - 256;
        int dir = bc / 100, c = bc % 100;
        if (tid < 64) sEmb[tid] = Wce[c * 64 + tid];
        __syncthreads();
        int u = tid >> 2, g = tid & 3;
        const float* Wih = dir ? c_wih_b : c_wih_f;
        const float* cb = dir ? cb_b : cb_f;
        int row = g * 64 + u;
        float acc = cb[row];
        #pragma unroll 8
        for (int k = 0; k < 64; k++) acc = fmaf(Wih[row * 64 + k], sEmb[k], acc);
        g_P[dir][c][u][g] = acc;
    } else if (blk < 2504) {
        int id = (blk - 456) * 256 + tid;              // 524288
        int dir = id / 262144; int r = id % 262144;
        int k = r >> 10; int uq = r & 1023; int u = uq >> 2; int q = uq & 3;
        const float* W = dir ? w_whh_b : w_whh_f;
        g_WHP[dir][k][u][q] = W[(q * 256 + u) * 256 + k];
    } else if (blk < 5576) {
        int id = (blk - 2504) * 256 + tid;             // 786432
        int dir = id / 393216; int r = id % 393216;
        int gh = r / 196608; int r2 = r % 196608;
        int k = r2 >> 9; int up = r2 & 511; int u = up >> 1; int p = up & 1;
        int q = gh * 2 + p;
        const float* W = dir ? w_wih_b : w_wih_f;
        g_WIP2[dir][gh][k][u * 2 + p] = W[(q * 256 + u) * 384 + k];
    } else {
        int id = (blk - 5576) * 256 + tid;             // 262144
        int word = id >> 6;
        int k4 = id & 63;
        int idx = sent[word];
        float4 v = ((const float4*)Wwe)[idx * 64 + k4];
        ((float4*)g_x)[word * 96 + 32 + k4] = v;
    }
}

// ---------------- char BiLSTM: P-seeded, h-only recurrence (k=64) ----------------
#define CHAR_SMEM (65536 + 102400 + 32768 + 4096)
__global__ __launch_bounds__(256) void k_char(const int* __restrict__ charArr) {
    extern __shared__ float sm[];
    ulonglong2* sW2 = (ulonglong2*)sm;                               // [64 k][64 u]
    float4* sW4 = (float4*)sm;
    ulonglong2* sP2 = (ulonglong2*)(sm + 16384);                     // [100 c][64 u]
    float4* sP4 = (float4*)(sm + 16384);
    unsigned long long* sXH = (unsigned long long*)(sm + 41984);     // [8 w][8 wd][64]
    int* sIdx = (int*)(sm + 50176);                                  // [64][16]

    int dir = blockIdx.y;
    int tid = threadIdx.x, warp = tid >> 5, lane = tid & 31;

    const float4* gw = ((const float4*)g_cWP) + dir * (128 * 64);
    for (int i = tid; i < 4096; i += 256) sW4[i] = gw[(64 + (i >> 6)) * 64 + (i & 63)];
    const float4* gp = ((const float4*)g_P) + dir * 6400;
    for (int i = tid; i < 6400; i += 256) sP4[i] = gp[i];
    for (int i = tid; i < 1024; i += 256)
        sIdx[i] = charArr[(blockIdx.x * 64 + (i >> 4)) * CC + (i & 15)];
    for (int i = tid; i < 4096; i += 256) sXH[i] = 0ull;
    __syncthreads();

    unsigned long long* xh = sXH + warp * 512;        // [8 wd][64]
    const int* widx = sIdx + warp * 128;
    int wordBase = blockIdx.x * 64 + warp * 8;
    float cA[8] = {0,0,0,0,0,0,0,0}, cB[8] = {0,0,0,0,0,0,0,0};

    for (int t = 0; t < 16; t++) {
        int cidx = dir ? (15 - t) : t;
        unsigned long long aA01[8], aA23[8], aB01[8], aB23[8];
        #pragma unroll
        for (int wd = 0; wd < 8; wd++) {
            int c = widx[wd * 16 + cidx];
            ulonglong2 pa = sP2[c * 64 + lane];
            ulonglong2 pb = sP2[c * 64 + 32 + lane];
            aA01[wd] = pa.x; aA23[wd] = pa.y;
            aB01[wd] = pb.x; aB23[wd] = pb.y;
        }
        #pragma unroll 2
        for (int k = 0; k < 64; k++) {
            ulonglong2 wA = sW2[k * 64 + lane];
            ulonglong2 wB = sW2[k * 64 + 32 + lane];
            #pragma unroll
            for (int wd = 0; wd < 8; wd++) {
                unsigned long long xv = xh[wd * 64 + k];
                aA01[wd] = fma2(wA.x, xv, aA01[wd]);
                aA23[wd] = fma2(wA.y, xv, aA23[wd]);
                aB01[wd] = fma2(wB.x, xv, aB01[wd]);
                aB23[wd] = fma2(wB.y, xv, aB23[wd]);
            }
        }
        __syncwarp();
        #pragma unroll
        for (int wd = 0; wd < 8; wd++) {
            float i0, f0, gg0, o0;
            upk2(aA01[wd], i0, f0); upk2(aA23[wd], gg0, o0);
            cA[wd] = sig_a(f0) * cA[wd] + sig_a(i0) * tanh_a(gg0);
            float hA = sig_a(o0) * tanh_a(cA[wd]);
            upk2(aB01[wd], i0, f0); upk2(aB23[wd], gg0, o0);
            cB[wd] = sig_a(f0) * cB[wd] + sig_a(i0) * tanh_a(gg0);
            float hB = sig_a(o0) * tanh_a(cB[wd]);
            xh[wd * 64 + lane] = pk2(hA, hA);
            xh[wd * 64 + 32 + lane] = pk2(hB, hB);
        }
        __syncwarp();
    }
    #pragma unroll
    for (int wd = 0; wd < 8; wd++) {
        int n = wordBase + wd;
        int b = n >> 7, s = n & 127;
        float* dst = g_x + (s * BB + b) * 384 + dir * 64;
        float hA, hB, d0;
        upk2(xh[wd * 64 + lane], hA, d0);
        upk2(xh[wd * 64 + 32 + lane], hB, d0);
        dst[lane] = hA;
        dst[32 + lane] = hB;
    }
}

// ---------------- x-part GEMM: gate-split, all 32 batches, 4-deep prefetch -------------
// grid (128 s, 2 dir, 2 gate-halves), 256 threads (u). Each block: 2 gates x 32 batches.
__global__ __launch_bounds__(256) void k_pre2(const float* __restrict__ wb_f,
                                              const float* __restrict__ wb_b) {
    __shared__ unsigned long long sxp[16][384];     // {x[b], x[b+16]} - 48KB
    int s = blockIdx.x, dir = blockIdx.y, gh = blockIdx.z;
    int u = threadIdx.x;
    const float* xsrc = g_x + s * BB * 384;
    for (int i = u; i < 16 * 384; i += 256) {
        int b2 = i / 384, k = i % 384;
        sxp[b2][k] = pk2(xsrc[b2 * 384 + k], xsrc[(b2 + 16) * 384 + k]);
    }
    __syncthreads();

    unsigned long long accA[16], accB[16];
    #pragma unroll
    for (int p = 0; p < 16; p++) { accA[p] = 0ull; accB[p] = 0ull; }

    const unsigned long long* Wp =
        (const unsigned long long*)(&g_WIP2[dir][gh][0][0]) + u;    // row stride = 256 u64
    unsigned long long wq[4];
    #pragma unroll
    for (int j = 0; j < 4; j++) wq[j] = Wp[j * 256];
    for (int k = 0; k < 384; k++) {
        unsigned long long w = wq[k & 3];
        if (k + 4 < 384) wq[k & 3] = Wp[(k + 4) * 256];
        float wg0, wg1;
        upk2(w, wg0, wg1);
        unsigned long long wA = pk2(wg0, wg0), wB = pk2(wg1, wg1);
        #pragma unroll
        for (int p = 0; p < 16; p++) {
            unsigned long long xv = sxp[p][k];
            accA[p] = fma2(wA, xv, accA[p]);
            accB[p] = fma2(wB, xv, accB[p]);
        }
    }
    const float* wb = dir ? wb_b : wb_f;
    float bA = wb[(2 * gh) * 256 + u];
    float bB = wb[(2 * gh + 1) * 256 + u];
    float2* dst = ((float2*)g_pre) + (size_t)((dir * SS + s) * BB) * 512;
    #pragma unroll
    for (int p = 0; p < 16; p++) {
        float a0, a1, b0, b1;
        upk2(accA[p], a0, a1);
        upk2(accB[p], b0, b1);
        dst[p * 512 + u * 2 + gh]        = make_float2(a0 + bA, b0 + bB);
        dst[(p + 16) * 512 + u * 2 + gh] = make_float2(a1 + bA, b1 + bB);
    }
}

// ---------------- word LSTM: 8-CTA cluster, SMEM Whh, st.async + tx-mbarrier sync --------
#define H2_OFF 131072
#define MBAR_OFF 147456
#define REC_SMEM (147456 + 64)
__global__ __launch_bounds__(128, 1) __cluster_dims__(8, 1, 1) void k_rec2() {
    extern __shared__ float smr[];
    ulonglong2* sW = (ulonglong2*)smr;                               // [k=256][u_loc=32]
    unsigned long long* h2 = (unsigned long long*)(smr + 32768);     // [2][4][256] {h,h}

    int cta = blockIdx.x;
    int rank = cta & 7, cid = cta >> 3;
    int dir = cid & 1, bg = cid >> 1;
    int tid = threadIdx.x;
    int u = tid >> 2, bl = tid & 3;
    int uG = rank * 32 + u;
    int bG = bg * 4 + bl;

    unsigned int sbase = smem_u32(smr);
    const float4* g4 = ((const float4*)g_WHP) + dir * 65536;
    float4* sW4 = (float4*)sW;
    for (int i = tid; i < 8192; i += 128) {
        int k = i >> 5, uu = i & 31;
        sW4[i] = g4[k * 256 + rank * 32 + uu];
    }
    for (int i = tid; i < 1024; i += 128) h2[i] = 0ull;
    if (tid == 0) {
        MBAR_INIT_(sbase + MBAR_OFF, 1);
        MBAR_INIT_(sbase + MBAR_OFF + 8, 1);
    }
    __syncthreads();
    CLUSTER_SYNC_();

    unsigned int rb[8];
    #pragma unroll
    for (int r = 0; r < 8; r++)
        asm("mapa.shared::cluster.u32 %0, %1, %2;" : "=r"(rb[r]) : "r"(sbase), "r"(r));

    const ulonglong2* pre2 = (const ulonglong2*)g_pre;
    float c = 0.f;
    int cur = 0;
    unsigned int ph0 = 0, ph1 = 0;
    int s0 = dir ? (SS - 1) : 0;
    ulonglong2 av = pre2[(size_t)((dir * SS + s0) * BB + bG) * 256 + uG];

    for (int t = 0; t < SS; t++) {
        int s = dir ? (SS - 1 - t) : t;
        unsigned long long a01 = av.x, a23 = av.y;
        if (t + 1 < SS) {
            int sn = dir ? (SS - 2 - t) : (t + 1);
            av = pre2[(size_t)((dir * SS + sn) * BB + bG) * 256 + uG];
        }
        unsigned long long b01 = 0ull, b23 = 0ull;
        const ulonglong2* hp2 = (const ulonglong2*)(h2 + cur * 1024 + bl * 256);
        #pragma unroll 8
        for (int k2 = 0; k2 < 128; k2++) {
            ulonglong2 w0 = sW[(2 * k2) * 32 + u];
            ulonglong2 w1 = sW[(2 * k2 + 1) * 32 + u];
            ulonglong2 hh = hp2[k2];
            a01 = fma2(w0.x, hh.x, a01);
            a23 = fma2(w0.y, hh.x, a23);
            b01 = fma2(w1.x, hh.y, b01);
            b23 = fma2(w1.y, hh.y, b23);
        }
        a01 = add2(a01, b01);
        a23 = add2(a23, b23);
        float gi, gf, gg, go;
        upk2(a01, gi, gf); upk2(a23, gg, go);
        c = sig_a(gf) * c + sig_a(gi) * tanh_a(gg);
        float h = sig_a(go) * tanh_a(c);
        g_out[(s * BB + bG) * 512 + dir * 256 + uG] = h;

        if (t + 1 < SS) {
            int nxt = cur ^ 1;
            if (tid == 0) MBAR_EXPECT_(sbase + MBAR_OFF + nxt * 8, 8192);
            unsigned long long hp = pk2(h, h);
            unsigned int hoff = (unsigned)(H2_OFF + (nxt * 1024 + bl * 256 + uG) * 8);
            unsigned int moff = (unsigned)(MBAR_OFF + nxt * 8);
            #pragma unroll
            for (int r = 0; r < 8; r++)
                ST_ASYNC64_(rb[r] + hoff, hp, rb[r] + moff);
            if (nxt == 0) { mbar_wait(sbase + MBAR_OFF, ph0); ph0 ^= 1; }
            else          { mbar_wait(sbase + MBAR_OFF + 8, ph1); ph1 ^= 1; }
            cur = nxt;
        }
    }
}

// ---------------- emissions ----------------
__global__ __launch_bounds__(544) void k_em(const float* __restrict__ emW,
                                            const float* __restrict__ emb) {
    extern __shared__ float sm[];
    float* sO = sm;                // [32][513]
    float* sE = sm + 32 * 513;     // [17][513]
    int s = blockIdx.x, tid = threadIdx.x;
    const float* osrc = g_out + s * BB * 512;
    for (int i = tid; i < 32 * 512; i += 544) sO[(i >> 9) * 513 + (i & 511)] = osrc[i];
    for (int i = tid; i < 17 * 512; i += 544) sE[(i / 512) * 513 + (i % 512)] = emW[i];
    __syncthreads();
    int b = tid / 17, j = tid % 17;
    const float* ro = sO + b * 513;
    const float* rw = sE + j * 513;
    float acc = emb[j];
    #pragma unroll 8
    for (int k = 0; k < 512; k++) acc = fmaf(ro[k], rw[k], acc);
    g_em[(s * BB + b) * NT + j] = acc;
}

// ---------------- CRF ----------------
__global__ void k_crf(const int* __restrict__ tags, const float* __restrict__ trans,
                      const float* __restrict__ startv, const float* __restrict__ endv) {
    __shared__ float sE[NT][18], sT[NT][18], sU[32];
    int b = blockIdx.x, lane = threadIdx.x;
    for (int i = lane; i < NT * NT; i += 32) {
        float v = trans[i];
        sT[i / NT][i % NT] = v;
        sE[i / NT][i % NT] = expf(v);
    }
    __syncwarp();
    float alpha = -1e30f;
    if (lane < NT) alpha = startv[lane] + g_em[b * NT + lane];
    float emv = (lane < NT) ? g_em[(BB + b) * NT + lane] : 0.f;
    for (int t = 1; t < SS; t++) {
        float emn = (t + 1 < SS && lane < NT) ? g_em[((t + 1) * BB + b) * NT + lane] : 0.f;
        float m = alpha;
        #pragma unroll
        for (int o = 16; o > 0; o >>= 1) m = fmaxf(m, __shfl_xor_sync(0xffffffffu, m, o));
        sU[lane] = expf(alpha - m);
        __syncwarp();
        if (lane < NT) {
            float ssum = 0.f;
            #pragma unroll
            for (int i = 0; i < NT; i++) ssum = fmaf(sU[i], sE[i][lane], ssum);
            alpha = m + logf(ssum) + emv;
        }
        __syncwarp();
        emv = emn;
    }
    float v = (lane < NT) ? (alpha + endv[lane]) : -1e30f;
    float m2 = v;
    #pragma unroll
    for (int o = 16; o > 0; o >>= 1) m2 = fmaxf(m2, __shfl_xor_sync(0xffffffffu, m2, o));
    float e2 = expf(v - m2);
    #pragma unroll
    for (int o = 16; o > 0; o >>= 1) e2 += __shfl_xor_sync(0xffffffffu, e2, o);
    float den = m2 + logf(e2);

    float part = 0.f;
    for (int t = lane; t < SS; t += 32) {
        int tg = tags[t * BB + b];
        part += g_em[(t * BB + b) * NT + tg];
        if (t > 0) part += sT[tags[(t - 1) * BB + b]][tg];
    }
    #pragma unroll
    for (int o = 16; o > 0; o >>= 1) part += __shfl_xor_sync(0xffffffffu, part, o);
    if (lane == 0) {
        float num = part + startv[tags[b]] + endv[tags[(SS - 1) * BB + b]];
        g_part[b] = num - den;
    }
}

__global__ void k_final(float* out) {
    int lane = threadIdx.x;
    float v = g_part[lane];
    #pragma unroll
    for (int o = 16; o > 0; o >>= 1) v += __shfl_xor_sync(0xffffffffu, v, o);
    if (lane == 0) out[0] = -v;
}

// ---------------- launch ----------------
extern "C" void kernel_launch(void* const* d_in, const int* in_sizes, int n_in,
                              void* d_out, int out_size) {
    const int* sent = (const int*)d_in[0];
    const int* ch   = (const int*)d_in[1];
    const int* tags = (const int*)d_in[2];
    const float* Wwe = (const float*)d_in[3];
    const float* Wce = (const float*)d_in[4];
    const float* c_Wih_f = (const float*)d_in[5];
    const float* c_Whh_f = (const float*)d_in[6];
    const float* c_b_f   = (const float*)d_in[7];
    const float* c_Wih_b = (const float*)d_in[8];
    const float* c_Whh_b = (const float*)d_in[9];
    const float* c_b_b   = (const float*)d_in[10];
    const float* w_Wih_f = (const float*)d_in[11];
    const float* w_Whh_f = (const float*)d_in[12];
    const float* w_b_f   = (const float*)d_in[13];
    const float* w_Wih_b = (const float*)d_in[14];
    const float* w_Whh_b = (const float*)d_in[15];
    const float* w_b_b   = (const float*)d_in[16];
    const float* emW  = (const float*)d_in[17];
    const float* emb  = (const float*)d_in[18];
    const float* trans  = (const float*)d_in[19];
    const float* startv = (const float*)d_in[20];
    const float* endv   = (const float*)d_in[21];

    const int EM_SMEM = (32 * 513 + 17 * 513) * 4;
    cudaFuncSetAttribute(k_char, cudaFuncAttributeMaxDynamicSharedMemorySize, CHAR_SMEM);
    cudaFuncSetAttribute(k_rec2, cudaFuncAttributeMaxDynamicSharedMemorySize, REC_SMEM);
    cudaFuncSetAttribute(k_em, cudaFuncAttributeMaxDynamicSharedMemorySize, EM_SMEM);

    k_prep_all<<<6600, 256>>>(c_Wih_f, c_Whh_f, c_Wih_b, c_Whh_b, c_b_f, c_b_b,
                              w_Wih_f, w_Whh_f, w_Wih_b, w_Whh_b, Wce, sent, Wwe);
    k_char<<<dim3(64, 2), 256, CHAR_SMEM>>>(ch);
    k_pre2<<<dim3(128, 2, 2), 256>>>(w_b_f, w_b_b);
    k_rec2<<<128, 128, REC_SMEM>>>();
    k_em<<<128, 544, EM_SMEM>>>(emW, emb);
    k_crf<<<32, 32>>>(tags, trans, startv, endv);
    k_final<<<1, 32>>>((float*)d_out);
}